// round 6
// baseline (speedup 1.0000x reference)
#include <cuda_runtime.h>
#include <cuda_bf16.h>
#include <cstdint>

#define TOTAL_DIM 24976
#define NQ        97
#define THREADS   256

// ---- dynamic SMEM layout (bytes) ----
#define OFF_BIAS  0
#define OFF_GAMMA 2048
#define OFF_BETA  4096
#define OFF_SSUM  6144     // [32][8] f32
#define OFF_SSSQ  7168     // [32][8] f32
#define OFF_RST   8192     // [32][2] f32
#define OFF_A     8448     // 2 stages x 2 planes x 32 rows x 48B (16B-aligned pitch!)
#define A_STAGE   3072
#define A_PLANE   1536
#define A_ROWB    48
#define OFF_B     14592    // 2 stages x 2 planes x 16 rows x 1040B
#define B_STAGE   33280
#define B_PLANE   16640
#define B_ROWB    1040
#define SMEM_TOTAL 81152

// ---- prepped weights: bf16 hi/lo planes, [K][512] ----
__device__ uint4 g_bh0[400 * 512 * 2 / 16], g_bl0[400 * 512 * 2 / 16];
__device__ uint4 g_bh1[256 * 512 * 2 / 16], g_bl1[256 * 512 * 2 / 16];
__device__ uint4 g_bh2[256 * 512 * 2 / 16], g_bl2[256 * 512 * 2 / 16];

__device__ __forceinline__ uint32_t smem_u32(const void* p) {
    uint32_t a;
    asm("{ .reg .u64 t; cvta.to.shared.u64 t, %1; cvt.u32.u64 %0, t; }" : "=r"(a) : "l"(p));
    return a;
}
#define LDSM_X4(r0, r1, r2, r3, a) \
    asm volatile("ldmatrix.sync.aligned.m8n8.x4.shared.b16 {%0,%1,%2,%3}, [%4];" \
                 : "=r"(r0), "=r"(r1), "=r"(r2), "=r"(r3) : "r"(a))
#define LDSM_X4T(r0, r1, r2, r3, a) \
    asm volatile("ldmatrix.sync.aligned.m8n8.x4.trans.shared.b16 {%0,%1,%2,%3}, [%4];" \
                 : "=r"(r0), "=r"(r1), "=r"(r2), "=r"(r3) : "r"(a))
#define MMA16816(c, a0, a1, a2, a3, b0, b1) \
    asm volatile("mma.sync.aligned.m16n8k16.row.col.f32.bf16.bf16.f32 " \
                 "{%0,%1,%2,%3}, {%4,%5,%6,%7}, {%8,%9}, {%0,%1,%2,%3};" \
                 : "+f"((c)[0]), "+f"((c)[1]), "+f"((c)[2]), "+f"((c)[3]) \
                 : "r"(a0), "r"(a1), "r"(a2), "r"(a3), "r"(b0), "r"(b1))
__device__ __forceinline__ void cp16(uint32_t dst, const void* src) {
    asm volatile("cp.async.cg.shared.global [%0], [%1], 16;" :: "r"(dst), "l"(src));
}
__device__ __forceinline__ void bf16_split(float v, uint16_t& h, uint16_t& l) {
    __nv_bfloat16 hb = __float2bfloat16_rn(v);
    __nv_bfloat16 lb = __float2bfloat16_rn(v - __bfloat162float(hb));
    h = *(uint16_t*)&hb; l = *(uint16_t*)&lb;
}

// ================= fused GEMM + bias + ReLU + LayerNorm =================
// CTA: 32 rows x 512 cols, 8 warps, warp tile 32 x 64 (wn = wid). BK = 16.
template <int KSPLIT, int LVALID, int NCHUNK, int SEGOFF, int QOFF>
__device__ __forceinline__ void run_split(const float* __restrict__ x,
                                          const float* __restrict__ bias_g,
                                          const float* __restrict__ gamma_g,
                                          const float* __restrict__ beta_g,
                                          float* __restrict__ out,
                                          const uint4* __restrict__ wbh,
                                          const uint4* __restrict__ wbl,
                                          int tile) {
    extern __shared__ char smem[];
    const uint32_t sb = smem_u32(smem);
    const int tid = threadIdx.x, lane = tid & 31, wn = tid >> 5;
    const int row0 = tile * 32;

    float* bias_s = (float*)(smem + OFF_BIAS);
    float* gam_s  = (float*)(smem + OFF_GAMMA);
    float* bet_s  = (float*)(smem + OFF_BETA);
    for (int i = tid; i < 512; i += THREADS) {
        bias_s[i] = bias_g[i]; gam_s[i] = gamma_g[i]; bet_s[i] = beta_g[i];
    }

    // per-thread x mapping: row tid>>3 (0..31), float2 slot tid&7 (k = slot*2)
    const int xrow = tid >> 3, xc = tid & 7;
    const float* px;
    {
        int gr = row0 + xrow;
        int bb = gr / KSPLIT, jj = gr - bb * KSPLIT;
        px = x + (size_t)bb * TOTAL_DIM + SEGOFF + (size_t)jj * LVALID + xc * 2;
    }

    float acc[2][8][4];
#pragma unroll
    for (int mt = 0; mt < 2; mt++)
#pragma unroll
        for (int t = 0; t < 8; t++)
#pragma unroll
            for (int c = 0; c < 4; c++) acc[mt][t][c] = 0.f;

    const __nv_bfloat16* bh16 = (const __nv_bfloat16*)wbh;
    const __nv_bfloat16* bl16 = (const __nv_bfloat16*)wbl;

    // prologue: B chunk0 -> stage0 (16 rows x 512, 1024 float4/plane)
#pragma unroll
    for (int i = 0; i < 4; i++) {
        int fi = tid + i * THREADS;          // 0..1023
        int kr = fi >> 6, cc = fi & 63;
        cp16(sb + OFF_B + kr * B_ROWB + cc * 16, bh16 + (size_t)kr * 512 + cc * 8);
        cp16(sb + OFF_B + B_PLANE + kr * B_ROWB + cc * 16, bl16 + (size_t)kr * 512 + cc * 8);
    }
    asm volatile("cp.async.commit_group;" ::: "memory");

    float2 xv = *(const float2*)(px);

    for (int c = 0; c < NCHUNK; c++) {
        const int s = c & 1;

        // STS A(c): split to bf16 hi/lo planes (one u32 per plane per thread)
        {
            uint16_t h0, h1, l0, l1;
            bf16_split(xv.x, h0, l0); bf16_split(xv.y, h1, l1);
            uint32_t ph = (uint32_t)h0 | ((uint32_t)h1 << 16);
            uint32_t pl = (uint32_t)l0 | ((uint32_t)l1 << 16);
            uint32_t off = (uint32_t)(xrow * A_ROWB + xc * 4);
            *(uint32_t*)(smem + OFF_A + s * A_STAGE + off) = ph;
            *(uint32_t*)(smem + OFF_A + s * A_STAGE + A_PLANE + off) = pl;
        }

        asm volatile("cp.async.wait_group 0;" ::: "memory");
        __syncthreads();

        // issue next chunk's loads
        if (c + 1 < NCHUNK) {
            const uint32_t bDst = sb + OFF_B + (s ^ 1) * B_STAGE;
            const size_t kbase = (size_t)(c + 1) * 16 * 512;
#pragma unroll
            for (int i = 0; i < 4; i++) {
                int fi = tid + i * THREADS;
                int kr = fi >> 6, cc = fi & 63;
                cp16(bDst + kr * B_ROWB + cc * 16, bh16 + kbase + (size_t)kr * 512 + cc * 8);
                cp16(bDst + B_PLANE + kr * B_ROWB + cc * 16, bl16 + kbase + (size_t)kr * 512 + cc * 8);
            }
            asm volatile("cp.async.commit_group;" ::: "memory");
            xv = *(const float2*)(px + (c + 1) * 16);
        }

        // ---- compute stage s: 12 ldsm + 48 MMA ----
        const uint32_t aH = sb + OFF_A + s * A_STAGE;
        const uint32_t aL = aH + A_PLANE;
        const uint32_t bH = sb + OFF_B + s * B_STAGE;
        const uint32_t bL = bH + B_PLANE;

        uint32_t ah[2][4], al[2][4];
        const uint32_t acol2 = (uint32_t)(((lane >> 4) << 3) * 2);
#pragma unroll
        for (int mt = 0; mt < 2; mt++) {
            uint32_t aoff = (uint32_t)((mt * 16 + (lane & 15)) * A_ROWB) + acol2;
            LDSM_X4(ah[mt][0], ah[mt][1], ah[mt][2], ah[mt][3], aH + aoff);
            LDSM_X4(al[mt][0], al[mt][1], al[mt][2], al[mt][3], aL + aoff);
        }
        const uint32_t brow = (uint32_t)(lane & 15);
#pragma unroll
        for (int g = 0; g < 4; g++) {
            const uint32_t bcol = (uint32_t)(wn * 64 + g * 16 + ((lane >> 4) << 3));
            const uint32_t boff = brow * B_ROWB + bcol * 2;
            uint32_t b0, b1, b2, b3, c0, c1, c2, c3;
            LDSM_X4T(b0, b1, b2, b3, bH + boff);
            LDSM_X4T(c0, c1, c2, c3, bL + boff);
#pragma unroll
            for (int mt = 0; mt < 2; mt++) {
                MMA16816(acc[mt][2 * g],     ah[mt][0], ah[mt][1], ah[mt][2], ah[mt][3], b0, b1);
                MMA16816(acc[mt][2 * g + 1], ah[mt][0], ah[mt][1], ah[mt][2], ah[mt][3], b2, b3);
                MMA16816(acc[mt][2 * g],     al[mt][0], al[mt][1], al[mt][2], al[mt][3], b0, b1);
                MMA16816(acc[mt][2 * g + 1], al[mt][0], al[mt][1], al[mt][2], al[mt][3], b2, b3);
                MMA16816(acc[mt][2 * g],     ah[mt][0], ah[mt][1], ah[mt][2], ah[mt][3], c0, c1);
                MMA16816(acc[mt][2 * g + 1], ah[mt][0], ah[mt][1], ah[mt][2], ah[mt][3], c2, c3);
            }
        }
    }

    // ================= epilogue: bias + ReLU + LN =================
    float* ssum = (float*)(smem + OFF_SSUM);
    float* sssq = (float*)(smem + OFF_SSSQ);
    float* rst  = (float*)(smem + OFF_RST);

#pragma unroll
    for (int mt = 0; mt < 2; mt++) {
        float sum0 = 0.f, ssq0 = 0.f, sum1 = 0.f, ssq1 = 0.f;
#pragma unroll
        for (int t = 0; t < 8; t++) {
            int cb = wn * 64 + t * 8 + (lane & 3) * 2;
            float b0v = bias_s[cb], b1v = bias_s[cb + 1];
            float h;
            h = fmaxf(acc[mt][t][0] + b0v, 0.f); acc[mt][t][0] = h; sum0 += h; ssq0 += h * h;
            h = fmaxf(acc[mt][t][1] + b1v, 0.f); acc[mt][t][1] = h; sum0 += h; ssq0 += h * h;
            h = fmaxf(acc[mt][t][2] + b0v, 0.f); acc[mt][t][2] = h; sum1 += h; ssq1 += h * h;
            h = fmaxf(acc[mt][t][3] + b1v, 0.f); acc[mt][t][3] = h; sum1 += h; ssq1 += h * h;
        }
#pragma unroll
        for (int o = 1; o <= 2; o <<= 1) {
            sum0 += __shfl_xor_sync(0xffffffffu, sum0, o);
            ssq0 += __shfl_xor_sync(0xffffffffu, ssq0, o);
            sum1 += __shfl_xor_sync(0xffffffffu, sum1, o);
            ssq1 += __shfl_xor_sync(0xffffffffu, ssq1, o);
        }
        if ((lane & 3) == 0) {
            int r0 = mt * 16 + (lane >> 2);
            ssum[r0 * 8 + wn] = sum0;       sssq[r0 * 8 + wn] = ssq0;
            ssum[(r0 + 8) * 8 + wn] = sum1; sssq[(r0 + 8) * 8 + wn] = ssq1;
        }
    }
    __syncthreads();
    if (tid < 32) {
        float s = 0.f, q = 0.f;
#pragma unroll
        for (int i = 0; i < 8; i++) { s += ssum[tid * 8 + i]; q += sssq[tid * 8 + i]; }
        float mean = s * (1.f / 512.f);
        float var  = q * (1.f / 512.f) - mean * mean;
        rst[tid * 2] = mean;
        rst[tid * 2 + 1] = rsqrtf(var + 1e-5f);
    }
    __syncthreads();

#pragma unroll
    for (int mt = 0; mt < 2; mt++) {
        int r0 = mt * 16 + (lane >> 2);
        float m0 = rst[r0 * 2], rs0 = rst[r0 * 2 + 1];
        float m1 = rst[(r0 + 8) * 2], rs1 = rst[(r0 + 8) * 2 + 1];
        int gr0 = row0 + r0, gr1 = gr0 + 8;
        int b0i = gr0 / KSPLIT, j0 = gr0 - b0i * KSPLIT;
        int b1i = gr1 / KSPLIT, j1 = gr1 - b1i * KSPLIT;
        float* o0 = out + ((size_t)b0i * NQ + QOFF + j0) * 512;
        float* o1 = out + ((size_t)b1i * NQ + QOFF + j1) * 512;
#pragma unroll
        for (int t = 0; t < 8; t++) {
            int cb = wn * 64 + t * 8 + (lane & 3) * 2;
            float g0 = gam_s[cb], g1 = gam_s[cb + 1];
            float e0 = bet_s[cb], e1 = bet_s[cb + 1];
            float2 v0 = make_float2((acc[mt][t][0] - m0) * rs0 * g0 + e0,
                                    (acc[mt][t][1] - m0) * rs0 * g1 + e1);
            float2 v1 = make_float2((acc[mt][t][2] - m1) * rs1 * g0 + e0,
                                    (acc[mt][t][3] - m1) * rs1 * g1 + e1);
            *(float2*)(o0 + cb) = v0;
            *(float2*)(o1 + cb) = v1;
        }
    }
}

__global__ void __launch_bounds__(THREADS, 2)
fused_kernel(const float* __restrict__ x,
             const float* b0, const float* g0, const float* be0,
             const float* b1, const float* g1, const float* be1,
             const float* b2, const float* g2, const float* be2,
             float* __restrict__ out) {
    const int blk = blockIdx.x;
    if (blk < 64)         run_split<1,  400, 25, 0,     0 >(x, b0, g0, be0, out, g_bh0, g_bl0, blk);
    else if (blk < 3904)  run_split<60, 256, 16, 400,   1 >(x, b1, g1, be1, out, g_bh1, g_bl1, blk - 64);
    else                  run_split<36, 256, 16, 15760, 61>(x, b2, g2, be2, out, g_bh2, g_bl2, blk - 3904);
}

// ================= weight prep: W f32 -> bf16 hi/lo planes =================
__device__ __forceinline__ void prep_one(const float* __restrict__ W, uint4* bh, uint4* bl,
                                         int idx) {
    float v = W[idx];
    uint16_t h, l;
    bf16_split(v, h, l);
    ((uint16_t*)bh)[idx] = h;
    ((uint16_t*)bl)[idx] = l;
}

__global__ void prep_kernel(const float* __restrict__ W0, const float* __restrict__ W1,
                            const float* __restrict__ W2) {
    const int idx = blockIdx.x * blockDim.x + threadIdx.x;
    const int T0 = 400 * 512, T1 = 256 * 512, T2 = 256 * 512;
    if (idx < T0)                prep_one(W0, g_bh0, g_bl0, idx);
    else if (idx < T0 + T1)      prep_one(W1, g_bh1, g_bl1, idx - T0);
    else if (idx < T0 + T1 + T2) prep_one(W2, g_bh2, g_bl2, idx - T0 - T1);
}

// ================= launch =================
extern "C" void kernel_launch(void* const* d_in, const int* in_sizes, int n_in,
                              void* d_out, int out_size) {
    (void)in_sizes; (void)n_in; (void)out_size;
    const float* x = (const float*)d_in[0];
    float* out = (float*)d_out;

    cudaFuncSetAttribute(fused_kernel, cudaFuncAttributeMaxDynamicSharedMemorySize, SMEM_TOTAL);

    const int prep_total = (400 + 256 + 256) * 512;
    prep_kernel<<<(prep_total + 255) / 256, 256>>>(
        (const float*)d_in[1], (const float*)d_in[5], (const float*)d_in[9]);

    fused_kernel<<<6208, THREADS, SMEM_TOTAL>>>(
        x,
        (const float*)d_in[2],  (const float*)d_in[3],  (const float*)d_in[4],
        (const float*)d_in[6],  (const float*)d_in[7],  (const float*)d_in[8],
        (const float*)d_in[10], (const float*)d_in[11], (const float*)d_in[12],
        out);
}

// round 7
// speedup vs baseline: 2.1820x; 2.1820x over previous
#include <cuda_runtime.h>
#include <cuda_fp16.h>
#include <cstdint>

#define TOTAL_DIM 24976
#define NQ        97
#define THREADS   512

// ---- dynamic SMEM layout (bytes) ----
#define OFF_BIAS  0
#define OFF_GAMMA 2048
#define OFF_BETA  4096
#define OFF_SSUM  6144     // [64][8] f32
#define OFF_SSSQ  8192     // [64][8] f32
#define OFF_RST   10240    // [64][2] f32
#define OFF_A     10752    // 2 stages x 2 planes x 64 rows x 80B
#define A_STAGE   10240
#define A_PLANE   5120
#define A_ROWB    80
#define OFF_B     31232    // 2 stages x 1 plane x 32 rows x 1040B
#define B_STAGE   33280
#define B_ROWB    1040
#define SMEM_TOTAL 97792

// ---- prepped weights: fp16 (single rounding), [Kpad][512] ----
__device__ uint4 g_w0[416 * 512 * 2 / 16];
__device__ uint4 g_w1[256 * 512 * 2 / 16];
__device__ uint4 g_w2[256 * 512 * 2 / 16];

__device__ __forceinline__ uint32_t smem_u32(const void* p) {
    uint32_t a;
    asm("{ .reg .u64 t; cvta.to.shared.u64 t, %1; cvt.u32.u64 %0, t; }" : "=r"(a) : "l"(p));
    return a;
}
#define LDSM_X4(r0, r1, r2, r3, a) \
    asm volatile("ldmatrix.sync.aligned.m8n8.x4.shared.b16 {%0,%1,%2,%3}, [%4];" \
                 : "=r"(r0), "=r"(r1), "=r"(r2), "=r"(r3) : "r"(a))
#define LDSM_X4T(r0, r1, r2, r3, a) \
    asm volatile("ldmatrix.sync.aligned.m8n8.x4.trans.shared.b16 {%0,%1,%2,%3}, [%4];" \
                 : "=r"(r0), "=r"(r1), "=r"(r2), "=r"(r3) : "r"(a))
#define MMA16816(c, a0, a1, a2, a3, b0, b1) \
    asm volatile("mma.sync.aligned.m16n8k16.row.col.f32.f16.f16.f32 " \
                 "{%0,%1,%2,%3}, {%4,%5,%6,%7}, {%8,%9}, {%0,%1,%2,%3};" \
                 : "+f"((c)[0]), "+f"((c)[1]), "+f"((c)[2]), "+f"((c)[3]) \
                 : "r"(a0), "r"(a1), "r"(a2), "r"(a3), "r"(b0), "r"(b1))
__device__ __forceinline__ void cp16(uint32_t dst, const void* src) {
    asm volatile("cp.async.cg.shared.global [%0], [%1], 16;" :: "r"(dst), "l"(src));
}
__device__ __forceinline__ void fp16_split(float v, uint16_t& h, uint16_t& l) {
    __half hb = __float2half_rn(v);
    __half lb = __float2half_rn(v - __half2float(hb));
    h = *(uint16_t*)&hb; l = *(uint16_t*)&lb;
}

// ================= fused GEMM + bias + ReLU + LayerNorm =================
// CTA: 64 rows x 512 cols, 16 warps, warp tile 32 x 64 (wm = wid&1, wn = wid>>1). BK = 32.
template <int KSPLIT, int LVALID, int NCHUNK, int SEGOFF, int QOFF>
__device__ __forceinline__ void run_split(const float* __restrict__ x,
                                          const float* __restrict__ bias_g,
                                          const float* __restrict__ gamma_g,
                                          const float* __restrict__ beta_g,
                                          float* __restrict__ out,
                                          const uint4* __restrict__ wph,
                                          int tile) {
    extern __shared__ char smem[];
    const uint32_t sb = smem_u32(smem);
    const int tid = threadIdx.x, lane = tid & 31, wid = tid >> 5;
    const int wm = wid & 1;        // row half: rows wm*32..+32
    const int wn = wid >> 1;       // col group: cols wn*64..+64
    const int row0 = tile * 64;

    float* bias_s = (float*)(smem + OFF_BIAS);
    float* gam_s  = (float*)(smem + OFF_GAMMA);
    float* bet_s  = (float*)(smem + OFF_BETA);
    for (int i = tid; i < 512; i += THREADS) {
        bias_s[i] = bias_g[i]; gam_s[i] = gamma_g[i]; bet_s[i] = beta_g[i];
    }

    // per-thread x mapping: one row (tid>>3), one float4 slot (tid&7)
    const int xrow = tid >> 3, xf4 = tid & 7;
    const float* px;
    {
        int gr = row0 + xrow;
        int bb = gr / KSPLIT, jj = gr - bb * KSPLIT;
        px = x + (size_t)bb * TOTAL_DIM + SEGOFF + (size_t)jj * LVALID + xf4 * 4;
    }

    float acc[2][8][4];
#pragma unroll
    for (int mt = 0; mt < 2; mt++)
#pragma unroll
        for (int t = 0; t < 8; t++)
#pragma unroll
            for (int c = 0; c < 4; c++) acc[mt][t][c] = 0.f;

    const __half* w16 = (const __half*)wph;

    // prologue: B chunk0 -> stage0 (32 rows x 512 halfs = 2048 float4)
#pragma unroll
    for (int i = 0; i < 4; i++) {
        int fi = tid + i * THREADS;          // 0..2047
        int kr = fi >> 6, cc = fi & 63;
        cp16(sb + OFF_B + kr * B_ROWB + cc * 16, w16 + (size_t)kr * 512 + cc * 8);
    }
    asm volatile("cp.async.commit_group;" ::: "memory");

    float4 xv;
    {
        int k0 = xf4 * 4;
        xv = (k0 + 4 <= LVALID) ? *(const float4*)(px) : make_float4(0.f, 0.f, 0.f, 0.f);
    }

    for (int c = 0; c < NCHUNK; c++) {
        const int s = c & 1;

        // STS A(c): split to fp16 hi/lo planes
        {
            uint16_t h0, h1, h2, h3, l0, l1, l2, l3;
            fp16_split(xv.x, h0, l0); fp16_split(xv.y, h1, l1);
            fp16_split(xv.z, h2, l2); fp16_split(xv.w, h3, l3);
            uint2 ph = make_uint2((uint32_t)h0 | ((uint32_t)h1 << 16),
                                  (uint32_t)h2 | ((uint32_t)h3 << 16));
            uint2 pl = make_uint2((uint32_t)l0 | ((uint32_t)l1 << 16),
                                  (uint32_t)l2 | ((uint32_t)l3 << 16));
            uint32_t off = (uint32_t)(xrow * A_ROWB + xf4 * 8);
            *(uint2*)(smem + OFF_A + s * A_STAGE + off) = ph;
            *(uint2*)(smem + OFF_A + s * A_STAGE + A_PLANE + off) = pl;
        }

        asm volatile("cp.async.wait_group 0;" ::: "memory");
        __syncthreads();

        // issue next chunk's loads
        if (c + 1 < NCHUNK) {
            const uint32_t bDst = sb + OFF_B + (s ^ 1) * B_STAGE;
            const size_t kbase = (size_t)(c + 1) * 32 * 512;
#pragma unroll
            for (int i = 0; i < 4; i++) {
                int fi = tid + i * THREADS;
                int kr = fi >> 6, cc = fi & 63;
                cp16(bDst + kr * B_ROWB + cc * 16, w16 + kbase + (size_t)kr * 512 + cc * 8);
            }
            asm volatile("cp.async.commit_group;" ::: "memory");
            int k0 = (c + 1) * 32 + xf4 * 4;
            xv = (k0 + 4 <= LVALID) ? *(const float4*)(px + (c + 1) * 32)
                                    : make_float4(0.f, 0.f, 0.f, 0.f);
        }

        // ---- compute stage s: 16 ldsm + 64 MMA ----
        const uint32_t aH = sb + OFF_A + s * A_STAGE;
        const uint32_t aL = aH + A_PLANE;
        const uint32_t bB = sb + OFF_B + s * B_STAGE;
#pragma unroll
        for (int ks = 0; ks < 2; ks++) {
            const uint32_t arow = (uint32_t)(wm * 32 + (lane & 15));
            const uint32_t acol = (uint32_t)(((lane >> 4) << 3) + ks * 16);
            uint32_t ah[2][4], al[2][4];
#pragma unroll
            for (int mt = 0; mt < 2; mt++) {
                uint32_t aoff = (arow + mt * 16) * A_ROWB + acol * 2;
                LDSM_X4(ah[mt][0], ah[mt][1], ah[mt][2], ah[mt][3], aH + aoff);
                LDSM_X4(al[mt][0], al[mt][1], al[mt][2], al[mt][3], aL + aoff);
            }
            const uint32_t brow = (uint32_t)(ks * 16 + (lane & 15));
#pragma unroll
            for (int g = 0; g < 4; g++) {
                const uint32_t bcol = (uint32_t)(wn * 64 + g * 16 + ((lane >> 4) << 3));
                const uint32_t boff = brow * B_ROWB + bcol * 2;
                uint32_t b0, b1, b2, b3;
                LDSM_X4T(b0, b1, b2, b3, bB + boff);
                // 4 independent chains, hi-pass then lo-pass (spacing 4)
                MMA16816(acc[0][2 * g],     ah[0][0], ah[0][1], ah[0][2], ah[0][3], b0, b1);
                MMA16816(acc[0][2 * g + 1], ah[0][0], ah[0][1], ah[0][2], ah[0][3], b2, b3);
                MMA16816(acc[1][2 * g],     ah[1][0], ah[1][1], ah[1][2], ah[1][3], b0, b1);
                MMA16816(acc[1][2 * g + 1], ah[1][0], ah[1][1], ah[1][2], ah[1][3], b2, b3);
                MMA16816(acc[0][2 * g],     al[0][0], al[0][1], al[0][2], al[0][3], b0, b1);
                MMA16816(acc[0][2 * g + 1], al[0][0], al[0][1], al[0][2], al[0][3], b2, b3);
                MMA16816(acc[1][2 * g],     al[1][0], al[1][1], al[1][2], al[1][3], b0, b1);
                MMA16816(acc[1][2 * g + 1], al[1][0], al[1][1], al[1][2], al[1][3], b2, b3);
            }
        }
    }

    // ================= epilogue: bias + ReLU + LN =================
    float* ssum = (float*)(smem + OFF_SSUM);
    float* sssq = (float*)(smem + OFF_SSSQ);
    float* rst  = (float*)(smem + OFF_RST);

#pragma unroll
    for (int mt = 0; mt < 2; mt++) {
        float sum0 = 0.f, ssq0 = 0.f, sum1 = 0.f, ssq1 = 0.f;
#pragma unroll
        for (int t = 0; t < 8; t++) {
            int cb = wn * 64 + t * 8 + (lane & 3) * 2;
            float b0v = bias_s[cb], b1v = bias_s[cb + 1];
            float h;
            h = fmaxf(acc[mt][t][0] + b0v, 0.f); acc[mt][t][0] = h; sum0 += h; ssq0 += h * h;
            h = fmaxf(acc[mt][t][1] + b1v, 0.f); acc[mt][t][1] = h; sum0 += h; ssq0 += h * h;
            h = fmaxf(acc[mt][t][2] + b0v, 0.f); acc[mt][t][2] = h; sum1 += h; ssq1 += h * h;
            h = fmaxf(acc[mt][t][3] + b1v, 0.f); acc[mt][t][3] = h; sum1 += h; ssq1 += h * h;
        }
#pragma unroll
        for (int o = 1; o <= 2; o <<= 1) {
            sum0 += __shfl_xor_sync(0xffffffffu, sum0, o);
            ssq0 += __shfl_xor_sync(0xffffffffu, ssq0, o);
            sum1 += __shfl_xor_sync(0xffffffffu, sum1, o);
            ssq1 += __shfl_xor_sync(0xffffffffu, ssq1, o);
        }
        if ((lane & 3) == 0) {
            int r0 = wm * 32 + mt * 16 + (lane >> 2);
            ssum[r0 * 8 + wn] = sum0;       sssq[r0 * 8 + wn] = ssq0;
            ssum[(r0 + 8) * 8 + wn] = sum1; sssq[(r0 + 8) * 8 + wn] = ssq1;
        }
    }
    __syncthreads();
    if (tid < 64) {
        float s = 0.f, q = 0.f;
#pragma unroll
        for (int i = 0; i < 8; i++) { s += ssum[tid * 8 + i]; q += sssq[tid * 8 + i]; }
        float mean = s * (1.f / 512.f);
        float var  = q * (1.f / 512.f) - mean * mean;
        rst[tid * 2] = mean;
        rst[tid * 2 + 1] = rsqrtf(var + 1e-5f);
    }
    __syncthreads();

#pragma unroll
    for (int mt = 0; mt < 2; mt++) {
        int r0 = wm * 32 + mt * 16 + (lane >> 2);
        float m0 = rst[r0 * 2], rs0 = rst[r0 * 2 + 1];
        float m1 = rst[(r0 + 8) * 2], rs1 = rst[(r0 + 8) * 2 + 1];
        int gr0 = row0 + r0, gr1 = gr0 + 8;
        int b0i = gr0 / KSPLIT, j0 = gr0 - b0i * KSPLIT;
        int b1i = gr1 / KSPLIT, j1 = gr1 - b1i * KSPLIT;
        float* o0 = out + ((size_t)b0i * NQ + QOFF + j0) * 512;
        float* o1 = out + ((size_t)b1i * NQ + QOFF + j1) * 512;
#pragma unroll
        for (int t = 0; t < 8; t++) {
            int cb = wn * 64 + t * 8 + (lane & 3) * 2;
            float g0 = gam_s[cb], g1 = gam_s[cb + 1];
            float e0 = bet_s[cb], e1 = bet_s[cb + 1];
            float2 v0 = make_float2((acc[mt][t][0] - m0) * rs0 * g0 + e0,
                                    (acc[mt][t][1] - m0) * rs0 * g1 + e1);
            float2 v1 = make_float2((acc[mt][t][2] - m1) * rs1 * g0 + e0,
                                    (acc[mt][t][3] - m1) * rs1 * g1 + e1);
            *(float2*)(o0 + cb) = v0;
            *(float2*)(o1 + cb) = v1;
        }
    }
}

__global__ void __launch_bounds__(THREADS, 1)
fused_kernel(const float* __restrict__ x,
             const float* b0, const float* g0, const float* be0,
             const float* b1, const float* g1, const float* be1,
             const float* b2, const float* g2, const float* be2,
             float* __restrict__ out) {
    const int blk = blockIdx.x;
    if (blk < 32)         run_split<1,  400, 13, 0,     0 >(x, b0, g0, be0, out, g_w0, blk);
    else if (blk < 1952)  run_split<60, 256, 8,  400,   1 >(x, b1, g1, be1, out, g_w1, blk - 32);
    else                  run_split<36, 256, 8,  15760, 61>(x, b2, g2, be2, out, g_w2, blk - 1952);
}

// ================= weight prep: W f32 -> fp16 (zero-padded) =================
__device__ __forceinline__ void prep_one(const float* __restrict__ W, uint4* wp,
                                         int Lvalid, int idx) {
    int k = idx >> 9, n = idx & 511;
    float v = (k < Lvalid) ? W[(size_t)k * 512 + n] : 0.f;
    __half h = __float2half_rn(v);
    ((uint16_t*)wp)[idx] = *(uint16_t*)&h;
}

__global__ void prep_kernel(const float* __restrict__ W0, const float* __restrict__ W1,
                            const float* __restrict__ W2) {
    const int idx = blockIdx.x * blockDim.x + threadIdx.x;
    const int T0 = 416 * 512, T1 = 256 * 512, T2 = 256 * 512;
    if (idx < T0)                prep_one(W0, g_w0, 400, idx);
    else if (idx < T0 + T1)      prep_one(W1, g_w1, 256, idx - T0);
    else if (idx < T0 + T1 + T2) prep_one(W2, g_w2, 256, idx - T0 - T1);
}

// ================= launch =================
extern "C" void kernel_launch(void* const* d_in, const int* in_sizes, int n_in,
                              void* d_out, int out_size) {
    (void)in_sizes; (void)n_in; (void)out_size;
    const float* x = (const float*)d_in[0];
    float* out = (float*)d_out;

    cudaFuncSetAttribute(fused_kernel, cudaFuncAttributeMaxDynamicSharedMemorySize, SMEM_TOTAL);

    const int prep_total = (416 + 256 + 256) * 512;
    prep_kernel<<<(prep_total + 255) / 256, 256>>>(
        (const float*)d_in[1], (const float*)d_in[5], (const float*)d_in[9]);

    fused_kernel<<<3104, THREADS, SMEM_TOTAL>>>(
        x,
        (const float*)d_in[2],  (const float*)d_in[3],  (const float*)d_in[4],
        (const float*)d_in[6],  (const float*)d_in[7],  (const float*)d_in[8],
        (const float*)d_in[10], (const float*)d_in[11], (const float*)d_in[12],
        out);
}

// round 8
// speedup vs baseline: 2.2148x; 1.0150x over previous
#include <cuda_runtime.h>
#include <cuda_fp16.h>
#include <cstdint>

#define TOTAL_DIM 24976
#define NQ        97
#define THREADS   512

// ---- dynamic SMEM layout (bytes) ----
#define OFF_BIAS  0
#define OFF_GAMMA 2048
#define OFF_BETA  4096
#define OFF_SSUM  6144     // [64][8] f32
#define OFF_SSSQ  8192     // [64][8] f32
#define OFF_RST   10240    // [64][2] f32
#define OFF_A     10752    // 2 stages x 2 planes x 64 rows x 144B
#define A_STAGE   18432
#define A_PLANE   9216
#define A_ROWB    144
#define OFF_B     47616    // 2 stages x 64 rows x 1040B
#define B_STAGE   66560
#define B_ROWB    1040
#define SMEM_TOTAL 180736

// ---- prepped weights: fp16 (single rounding), [Kpad][512] ----
__device__ uint4 g_w0[448 * 512 * 2 / 16];
__device__ uint4 g_w1[256 * 512 * 2 / 16];
__device__ uint4 g_w2[256 * 512 * 2 / 16];

__device__ __forceinline__ uint32_t smem_u32(const void* p) {
    uint32_t a;
    asm("{ .reg .u64 t; cvta.to.shared.u64 t, %1; cvt.u32.u64 %0, t; }" : "=r"(a) : "l"(p));
    return a;
}
#define LDSM_X4(r0, r1, r2, r3, a) \
    asm volatile("ldmatrix.sync.aligned.m8n8.x4.shared.b16 {%0,%1,%2,%3}, [%4];" \
                 : "=r"(r0), "=r"(r1), "=r"(r2), "=r"(r3) : "r"(a))
#define LDSM_X4T(r0, r1, r2, r3, a) \
    asm volatile("ldmatrix.sync.aligned.m8n8.x4.trans.shared.b16 {%0,%1,%2,%3}, [%4];" \
                 : "=r"(r0), "=r"(r1), "=r"(r2), "=r"(r3) : "r"(a))
#define MMA16816(c, a0, a1, a2, a3, b0, b1) \
    asm volatile("mma.sync.aligned.m16n8k16.row.col.f32.f16.f16.f32 " \
                 "{%0,%1,%2,%3}, {%4,%5,%6,%7}, {%8,%9}, {%0,%1,%2,%3};" \
                 : "+f"((c)[0]), "+f"((c)[1]), "+f"((c)[2]), "+f"((c)[3]) \
                 : "r"(a0), "r"(a1), "r"(a2), "r"(a3), "r"(b0), "r"(b1))
__device__ __forceinline__ void cp16(uint32_t dst, const void* src) {
    asm volatile("cp.async.cg.shared.global [%0], [%1], 16;" :: "r"(dst), "l"(src));
}
__device__ __forceinline__ void fp16_split(float v, uint16_t& h, uint16_t& l) {
    __half hb = __float2half_rn(v);
    __half lb = __float2half_rn(v - __half2float(hb));
    h = *(uint16_t*)&hb; l = *(uint16_t*)&lb;
}

// ================= fused GEMM + bias + ReLU + LayerNorm =================
// CTA: 64 rows x 512 cols, 16 warps, warp tile 32 x 64 (wm = wid&1, wn = wid>>1). BK = 64.
template <int KSPLIT, int LVALID, int NCHUNK, int SEGOFF, int QOFF>
__device__ __forceinline__ void run_split(const float* __restrict__ x,
                                          const float* __restrict__ bias_g,
                                          const float* __restrict__ gamma_g,
                                          const float* __restrict__ beta_g,
                                          float* __restrict__ out,
                                          const uint4* __restrict__ wph,
                                          int tile) {
    extern __shared__ char smem[];
    const uint32_t sb = smem_u32(smem);
    const int tid = threadIdx.x, lane = tid & 31, wid = tid >> 5;
    const int wm = wid & 1;        // row half: rows wm*32..+32
    const int wn = wid >> 1;       // col group: cols wn*64..+64
    const int row0 = tile * 64;

    float* bias_s = (float*)(smem + OFF_BIAS);
    float* gam_s  = (float*)(smem + OFF_GAMMA);
    float* bet_s  = (float*)(smem + OFF_BETA);
    for (int i = tid; i < 512; i += THREADS) {
        bias_s[i] = bias_g[i]; gam_s[i] = gamma_g[i]; bet_s[i] = beta_g[i];
    }

    // per-thread x mapping: one row (tid>>3), two float4 slots (tid&7, +32 halfs)
    const int xrow = tid >> 3, xf4 = tid & 7;
    const float* px;
    {
        int gr = row0 + xrow;
        int bb = gr / KSPLIT, jj = gr - bb * KSPLIT;
        px = x + (size_t)bb * TOTAL_DIM + SEGOFF + (size_t)jj * LVALID + xf4 * 4;
    }

    float acc[2][8][4];
#pragma unroll
    for (int mt = 0; mt < 2; mt++)
#pragma unroll
        for (int t = 0; t < 8; t++)
#pragma unroll
            for (int c = 0; c < 4; c++) acc[mt][t][c] = 0.f;

    const __half* w16 = (const __half*)wph;

    // prologue: B chunk0 -> stage0 (64 rows x 512 halfs = 4096 float4)
#pragma unroll
    for (int i = 0; i < 8; i++) {
        int fi = tid + i * THREADS;          // 0..4095
        int kr = fi >> 6, cc = fi & 63;
        cp16(sb + OFF_B + kr * B_ROWB + cc * 16, w16 + (size_t)kr * 512 + cc * 8);
    }
    asm volatile("cp.async.commit_group;" ::: "memory");

    float4 xv[2];
#pragma unroll
    for (int sl = 0; sl < 2; sl++) {
        int k0 = xf4 * 4 + sl * 32;
        xv[sl] = (LVALID % 64 == 0 || k0 + 4 <= LVALID) ? *(const float4*)(px + sl * 32)
                                                        : make_float4(0.f, 0.f, 0.f, 0.f);
    }

    for (int c = 0; c < NCHUNK; c++) {
        const int s = c & 1;

        // STS A(c): split to fp16 hi/lo planes
#pragma unroll
        for (int sl = 0; sl < 2; sl++) {
            uint16_t h0, h1, h2, h3, l0, l1, l2, l3;
            fp16_split(xv[sl].x, h0, l0); fp16_split(xv[sl].y, h1, l1);
            fp16_split(xv[sl].z, h2, l2); fp16_split(xv[sl].w, h3, l3);
            uint2 ph = make_uint2((uint32_t)h0 | ((uint32_t)h1 << 16),
                                  (uint32_t)h2 | ((uint32_t)h3 << 16));
            uint2 pl = make_uint2((uint32_t)l0 | ((uint32_t)l1 << 16),
                                  (uint32_t)l2 | ((uint32_t)l3 << 16));
            uint32_t off = (uint32_t)(xrow * A_ROWB + xf4 * 8 + sl * 64);
            *(uint2*)(smem + OFF_A + s * A_STAGE + off) = ph;
            *(uint2*)(smem + OFF_A + s * A_STAGE + A_PLANE + off) = pl;
        }

        asm volatile("cp.async.wait_group 0;" ::: "memory");
        __syncthreads();

        // issue next chunk's loads
        if (c + 1 < NCHUNK) {
            const uint32_t bDst = sb + OFF_B + (s ^ 1) * B_STAGE;
            const size_t kbase = (size_t)(c + 1) * 64 * 512;
#pragma unroll
            for (int i = 0; i < 8; i++) {
                int fi = tid + i * THREADS;
                int kr = fi >> 6, cc = fi & 63;
                cp16(bDst + kr * B_ROWB + cc * 16, w16 + kbase + (size_t)kr * 512 + cc * 8);
            }
            asm volatile("cp.async.commit_group;" ::: "memory");
#pragma unroll
            for (int sl = 0; sl < 2; sl++) {
                int k0 = (c + 1) * 64 + xf4 * 4 + sl * 32;
                xv[sl] = (LVALID % 64 == 0 || k0 + 4 <= LVALID)
                             ? *(const float4*)(px + (c + 1) * 64 + sl * 32)
                             : make_float4(0.f, 0.f, 0.f, 0.f);
            }
        }

        // ---- compute stage s: 4 ks x (8 A-ldsm + pipelined 4 B-ldsm + 32 MMA) ----
        const uint32_t aH = sb + OFF_A + s * A_STAGE;
        const uint32_t aL = aH + A_PLANE;
        const uint32_t bB = sb + OFF_B + s * B_STAGE;
#pragma unroll
        for (int ks = 0; ks < 4; ks++) {
            const uint32_t arow = (uint32_t)(wm * 32 + (lane & 15));
            const uint32_t acol = (uint32_t)(((lane >> 4) << 3) + ks * 16);
            uint32_t ah[2][4], al[2][4];
#pragma unroll
            for (int mt = 0; mt < 2; mt++) {
                uint32_t aoff = (arow + mt * 16) * A_ROWB + acol * 2;
                LDSM_X4(ah[mt][0], ah[mt][1], ah[mt][2], ah[mt][3], aH + aoff);
                LDSM_X4(al[mt][0], al[mt][1], al[mt][2], al[mt][3], aL + aoff);
            }
            const uint32_t brow = (uint32_t)(ks * 16 + (lane & 15));
            const uint32_t bbase = brow * B_ROWB + (uint32_t)(wn * 64 + ((lane >> 4) << 3)) * 2;

            uint32_t b[2][4];   // ping-pong B fragments
            LDSM_X4T(b[0][0], b[0][1], b[0][2], b[0][3], bB + bbase);
#pragma unroll
            for (int g = 0; g < 4; g++) {
                const int cur = g & 1, nxt = cur ^ 1;
                if (g < 3) {
                    LDSM_X4T(b[nxt][0], b[nxt][1], b[nxt][2], b[nxt][3],
                             bB + bbase + (uint32_t)(g + 1) * 32);
                }
                // 4 independent chains, hi-pass then lo-pass (spacing 4)
                MMA16816(acc[0][2 * g],     ah[0][0], ah[0][1], ah[0][2], ah[0][3], b[cur][0], b[cur][1]);
                MMA16816(acc[0][2 * g + 1], ah[0][0], ah[0][1], ah[0][2], ah[0][3], b[cur][2], b[cur][3]);
                MMA16816(acc[1][2 * g],     ah[1][0], ah[1][1], ah[1][2], ah[1][3], b[cur][0], b[cur][1]);
                MMA16816(acc[1][2 * g + 1], ah[1][0], ah[1][1], ah[1][2], ah[1][3], b[cur][2], b[cur][3]);
                MMA16816(acc[0][2 * g],     al[0][0], al[0][1], al[0][2], al[0][3], b[cur][0], b[cur][1]);
                MMA16816(acc[0][2 * g + 1], al[0][0], al[0][1], al[0][2], al[0][3], b[cur][2], b[cur][3]);
                MMA16816(acc[1][2 * g],     al[1][0], al[1][1], al[1][2], al[1][3], b[cur][0], b[cur][1]);
                MMA16816(acc[1][2 * g + 1], al[1][0], al[1][1], al[1][2], al[1][3], b[cur][2], b[cur][3]);
            }
        }
    }

    // ================= epilogue: bias + ReLU + LN =================
    float* ssum = (float*)(smem + OFF_SSUM);
    float* sssq = (float*)(smem + OFF_SSSQ);
    float* rst  = (float*)(smem + OFF_RST);

#pragma unroll
    for (int mt = 0; mt < 2; mt++) {
        float sum0 = 0.f, ssq0 = 0.f, sum1 = 0.f, ssq1 = 0.f;
#pragma unroll
        for (int t = 0; t < 8; t++) {
            int cb = wn * 64 + t * 8 + (lane & 3) * 2;
            float b0v = bias_s[cb], b1v = bias_s[cb + 1];
            float h;
            h = fmaxf(acc[mt][t][0] + b0v, 0.f); acc[mt][t][0] = h; sum0 += h; ssq0 += h * h;
            h = fmaxf(acc[mt][t][1] + b1v, 0.f); acc[mt][t][1] = h; sum0 += h; ssq0 += h * h;
            h = fmaxf(acc[mt][t][2] + b0v, 0.f); acc[mt][t][2] = h; sum1 += h; ssq1 += h * h;
            h = fmaxf(acc[mt][t][3] + b1v, 0.f); acc[mt][t][3] = h; sum1 += h; ssq1 += h * h;
        }
#pragma unroll
        for (int o = 1; o <= 2; o <<= 1) {
            sum0 += __shfl_xor_sync(0xffffffffu, sum0, o);
            ssq0 += __shfl_xor_sync(0xffffffffu, ssq0, o);
            sum1 += __shfl_xor_sync(0xffffffffu, sum1, o);
            ssq1 += __shfl_xor_sync(0xffffffffu, ssq1, o);
        }
        if ((lane & 3) == 0) {
            int r0 = wm * 32 + mt * 16 + (lane >> 2);
            ssum[r0 * 8 + wn] = sum0;       sssq[r0 * 8 + wn] = ssq0;
            ssum[(r0 + 8) * 8 + wn] = sum1; sssq[(r0 + 8) * 8 + wn] = ssq1;
        }
    }
    __syncthreads();
    if (tid < 64) {
        float s = 0.f, q = 0.f;
#pragma unroll
        for (int i = 0; i < 8; i++) { s += ssum[tid * 8 + i]; q += sssq[tid * 8 + i]; }
        float mean = s * (1.f / 512.f);
        float var  = q * (1.f / 512.f) - mean * mean;
        rst[tid * 2] = mean;
        rst[tid * 2 + 1] = rsqrtf(var + 1e-5f);
    }
    __syncthreads();

#pragma unroll
    for (int mt = 0; mt < 2; mt++) {
        int r0 = wm * 32 + mt * 16 + (lane >> 2);
        float m0 = rst[r0 * 2], rs0 = rst[r0 * 2 + 1];
        float m1 = rst[(r0 + 8) * 2], rs1 = rst[(r0 + 8) * 2 + 1];
        int gr0 = row0 + r0, gr1 = gr0 + 8;
        int b0i = gr0 / KSPLIT, j0 = gr0 - b0i * KSPLIT;
        int b1i = gr1 / KSPLIT, j1 = gr1 - b1i * KSPLIT;
        float* o0 = out + ((size_t)b0i * NQ + QOFF + j0) * 512;
        float* o1 = out + ((size_t)b1i * NQ + QOFF + j1) * 512;
#pragma unroll
        for (int t = 0; t < 8; t++) {
            int cb = wn * 64 + t * 8 + (lane & 3) * 2;
            float g0 = gam_s[cb], g1 = gam_s[cb + 1];
            float e0 = bet_s[cb], e1 = bet_s[cb + 1];
            float2 v0 = make_float2((acc[mt][t][0] - m0) * rs0 * g0 + e0,
                                    (acc[mt][t][1] - m0) * rs0 * g1 + e1);
            float2 v1 = make_float2((acc[mt][t][2] - m1) * rs1 * g0 + e0,
                                    (acc[mt][t][3] - m1) * rs1 * g1 + e1);
            *(float2*)(o0 + cb) = v0;
            *(float2*)(o1 + cb) = v1;
        }
    }
}

__global__ void __launch_bounds__(THREADS, 1)
fused_kernel(const float* __restrict__ x,
             const float* b0, const float* g0, const float* be0,
             const float* b1, const float* g1, const float* be1,
             const float* b2, const float* g2, const float* be2,
             float* __restrict__ out) {
    const int blk = blockIdx.x;
    if (blk < 32)         run_split<1,  400, 7, 0,     0 >(x, b0, g0, be0, out, g_w0, blk);
    else if (blk < 1952)  run_split<60, 256, 4, 400,   1 >(x, b1, g1, be1, out, g_w1, blk - 32);
    else                  run_split<36, 256, 4, 15760, 61>(x, b2, g2, be2, out, g_w2, blk - 1952);
}

// ================= weight prep: W f32 -> fp16 (zero-padded) =================
__device__ __forceinline__ void prep_one(const float* __restrict__ W, uint4* wp,
                                         int Lvalid, int idx) {
    int k = idx >> 9, n = idx & 511;
    float v = (k < Lvalid) ? W[(size_t)k * 512 + n] : 0.f;
    __half h = __float2half_rn(v);
    ((uint16_t*)wp)[idx] = *(uint16_t*)&h;
}

__global__ void prep_kernel(const float* __restrict__ W0, const float* __restrict__ W1,
                            const float* __restrict__ W2) {
    const int idx = blockIdx.x * blockDim.x + threadIdx.x;
    const int T0 = 448 * 512, T1 = 256 * 512, T2 = 256 * 512;
    if (idx < T0)                prep_one(W0, g_w0, 400, idx);
    else if (idx < T0 + T1)      prep_one(W1, g_w1, 256, idx - T0);
    else if (idx < T0 + T1 + T2) prep_one(W2, g_w2, 256, idx - T0 - T1);
}

// ================= launch =================
extern "C" void kernel_launch(void* const* d_in, const int* in_sizes, int n_in,
                              void* d_out, int out_size) {
    (void)in_sizes; (void)n_in; (void)out_size;
    const float* x = (const float*)d_in[0];
    float* out = (float*)d_out;

    cudaFuncSetAttribute(fused_kernel, cudaFuncAttributeMaxDynamicSharedMemorySize, SMEM_TOTAL);

    const int prep_total = (448 + 256 + 256) * 512;
    prep_kernel<<<(prep_total + 255) / 256, 256>>>(
        (const float*)d_in[1], (const float*)d_in[5], (const float*)d_in[9]);

    fused_kernel<<<3104, THREADS, SMEM_TOTAL>>>(
        x,
        (const float*)d_in[2],  (const float*)d_in[3],  (const float*)d_in[4],
        (const float*)d_in[6],  (const float*)d_in[7],  (const float*)d_in[8],
        (const float*)d_in[10], (const float*)d_in[11], (const float*)d_in[12],
        out);
}

// round 9
// speedup vs baseline: 2.9424x; 1.3285x over previous
#include <cuda_runtime.h>
#include <cuda_fp16.h>
#include <cstdint>

#define TOTAL_DIM 24976
#define NQ        97
#define THREADS   512

// ---- dynamic SMEM layout (bytes) ----
#define OFF_BIAS  0
#define OFF_GAMMA 2048
#define OFF_BETA  4096
#define OFF_SSUM  6144     // [64][8] f32
#define OFF_SSSQ  8192     // [64][8] f32
#define OFF_RST   10240    // [64][2] f32
#define OFF_A     10752    // 2 stages x 64 rows x 144B (single fp16 plane)
#define A_STAGE   9216
#define A_ROWB    144
#define OFF_B     29184    // 2 stages x 64 rows x 1040B
#define B_STAGE   66560
#define B_ROWB    1040
#define SMEM_TOTAL 162304

// ---- prepped weights: fp16 (single rounding), [Kpad][512] ----
__device__ uint4 g_w0[448 * 512 * 2 / 16];
__device__ uint4 g_w1[256 * 512 * 2 / 16];
__device__ uint4 g_w2[256 * 512 * 2 / 16];

__device__ __forceinline__ uint32_t smem_u32(const void* p) {
    uint32_t a;
    asm("{ .reg .u64 t; cvta.to.shared.u64 t, %1; cvt.u32.u64 %0, t; }" : "=r"(a) : "l"(p));
    return a;
}
#define LDSM_X4(r0, r1, r2, r3, a) \
    asm volatile("ldmatrix.sync.aligned.m8n8.x4.shared.b16 {%0,%1,%2,%3}, [%4];" \
                 : "=r"(r0), "=r"(r1), "=r"(r2), "=r"(r3) : "r"(a))
#define LDSM_X4T(r0, r1, r2, r3, a) \
    asm volatile("ldmatrix.sync.aligned.m8n8.x4.trans.shared.b16 {%0,%1,%2,%3}, [%4];" \
                 : "=r"(r0), "=r"(r1), "=r"(r2), "=r"(r3) : "r"(a))
#define MMA16816(c, a0, a1, a2, a3, b0, b1) \
    asm volatile("mma.sync.aligned.m16n8k16.row.col.f32.f16.f16.f32 " \
                 "{%0,%1,%2,%3}, {%4,%5,%6,%7}, {%8,%9}, {%0,%1,%2,%3};" \
                 : "+f"((c)[0]), "+f"((c)[1]), "+f"((c)[2]), "+f"((c)[3]) \
                 : "r"(a0), "r"(a1), "r"(a2), "r"(a3), "r"(b0), "r"(b1))
__device__ __forceinline__ void cp16(uint32_t dst, const void* src) {
    asm volatile("cp.async.cg.shared.global [%0], [%1], 16;" :: "r"(dst), "l"(src));
}

// ================= fused GEMM + bias + ReLU + LayerNorm =================
// CTA: 64 rows x 512 cols, 16 warps, warp tile 32 x 64 (wm = wid&1, wn = wid>>1). BK = 64.
template <int KSPLIT, int LVALID, int NCHUNK, int SEGOFF, int QOFF>
__device__ __forceinline__ void run_split(const float* __restrict__ x,
                                          const float* __restrict__ bias_g,
                                          const float* __restrict__ gamma_g,
                                          const float* __restrict__ beta_g,
                                          float* __restrict__ out,
                                          const uint4* __restrict__ wph,
                                          int tile) {
    extern __shared__ char smem[];
    const uint32_t sb = smem_u32(smem);
    const int tid = threadIdx.x, lane = tid & 31, wid = tid >> 5;
    const int wm = wid & 1;        // row half: rows wm*32..+32
    const int wn = wid >> 1;       // col group: cols wn*64..+64
    const int row0 = tile * 64;

    float* bias_s = (float*)(smem + OFF_BIAS);
    float* gam_s  = (float*)(smem + OFF_GAMMA);
    float* bet_s  = (float*)(smem + OFF_BETA);
    for (int i = tid; i < 512; i += THREADS) {
        bias_s[i] = bias_g[i]; gam_s[i] = gamma_g[i]; bet_s[i] = beta_g[i];
    }

    // per-thread x mapping: one row (tid>>3), two float4 slots (tid&7, +32 halfs)
    const int xrow = tid >> 3, xf4 = tid & 7;
    const float* px;
    {
        int gr = row0 + xrow;
        int bb = gr / KSPLIT, jj = gr - bb * KSPLIT;
        px = x + (size_t)bb * TOTAL_DIM + SEGOFF + (size_t)jj * LVALID + xf4 * 4;
    }

    float acc[2][8][4];
#pragma unroll
    for (int mt = 0; mt < 2; mt++)
#pragma unroll
        for (int t = 0; t < 8; t++)
#pragma unroll
            for (int c = 0; c < 4; c++) acc[mt][t][c] = 0.f;

    const __half* w16 = (const __half*)wph;

    // prologue: B chunk0 -> stage0 (64 rows x 512 halfs = 4096 float4)
#pragma unroll
    for (int i = 0; i < 8; i++) {
        int fi = tid + i * THREADS;          // 0..4095
        int kr = fi >> 6, cc = fi & 63;
        cp16(sb + OFF_B + kr * B_ROWB + cc * 16, w16 + (size_t)kr * 512 + cc * 8);
    }
    asm volatile("cp.async.commit_group;" ::: "memory");

    float4 xv[2];
#pragma unroll
    for (int sl = 0; sl < 2; sl++) {
        int k0 = xf4 * 4 + sl * 32;
        xv[sl] = (LVALID % 64 == 0 || k0 + 4 <= LVALID) ? *(const float4*)(px + sl * 32)
                                                        : make_float4(0.f, 0.f, 0.f, 0.f);
    }

    for (int c = 0; c < NCHUNK; c++) {
        const int s = c & 1;

        // STS A(c): round to fp16, single plane
#pragma unroll
        for (int sl = 0; sl < 2; sl++) {
            __half h0 = __float2half_rn(xv[sl].x), h1 = __float2half_rn(xv[sl].y);
            __half h2 = __float2half_rn(xv[sl].z), h3 = __float2half_rn(xv[sl].w);
            uint2 ph = make_uint2((uint32_t)*(uint16_t*)&h0 | ((uint32_t)*(uint16_t*)&h1 << 16),
                                  (uint32_t)*(uint16_t*)&h2 | ((uint32_t)*(uint16_t*)&h3 << 16));
            uint32_t off = (uint32_t)(xrow * A_ROWB + xf4 * 8 + sl * 64);
            *(uint2*)(smem + OFF_A + s * A_STAGE + off) = ph;
        }

        asm volatile("cp.async.wait_group 0;" ::: "memory");
        __syncthreads();

        // issue next chunk's loads
        if (c + 1 < NCHUNK) {
            const uint32_t bDst = sb + OFF_B + (s ^ 1) * B_STAGE;
            const size_t kbase = (size_t)(c + 1) * 64 * 512;
#pragma unroll
            for (int i = 0; i < 8; i++) {
                int fi = tid + i * THREADS;
                int kr = fi >> 6, cc = fi & 63;
                cp16(bDst + kr * B_ROWB + cc * 16, w16 + kbase + (size_t)kr * 512 + cc * 8);
            }
            asm volatile("cp.async.commit_group;" ::: "memory");
#pragma unroll
            for (int sl = 0; sl < 2; sl++) {
                int k0 = (c + 1) * 64 + xf4 * 4 + sl * 32;
                xv[sl] = (LVALID % 64 == 0 || k0 + 4 <= LVALID)
                             ? *(const float4*)(px + (c + 1) * 64 + sl * 32)
                             : make_float4(0.f, 0.f, 0.f, 0.f);
            }
        }

        // ---- compute stage s: 4 ks x (2 A-ldsm + pipelined 4 B-ldsm + 16 MMA) ----
        const uint32_t aB = sb + OFF_A + s * A_STAGE;
        const uint32_t bB = sb + OFF_B + s * B_STAGE;
#pragma unroll
        for (int ks = 0; ks < 4; ks++) {
            const uint32_t arow = (uint32_t)(wm * 32 + (lane & 15));
            const uint32_t acol = (uint32_t)(((lane >> 4) << 3) + ks * 16);
            uint32_t ah[2][4];
#pragma unroll
            for (int mt = 0; mt < 2; mt++) {
                uint32_t aoff = (arow + mt * 16) * A_ROWB + acol * 2;
                LDSM_X4(ah[mt][0], ah[mt][1], ah[mt][2], ah[mt][3], aB + aoff);
            }
            const uint32_t brow = (uint32_t)(ks * 16 + (lane & 15));
            const uint32_t bbase = brow * B_ROWB + (uint32_t)(wn * 64 + ((lane >> 4) << 3)) * 2;

            uint32_t b[2][4];   // ping-pong B fragments
            LDSM_X4T(b[0][0], b[0][1], b[0][2], b[0][3], bB + bbase);
#pragma unroll
            for (int g = 0; g < 4; g++) {
                const int cur = g & 1, nxt = cur ^ 1;
                if (g < 3) {
                    LDSM_X4T(b[nxt][0], b[nxt][1], b[nxt][2], b[nxt][3],
                             bB + bbase + (uint32_t)(g + 1) * 32);
                }
                // 4 independent accumulator chains per group
                MMA16816(acc[0][2 * g],     ah[0][0], ah[0][1], ah[0][2], ah[0][3], b[cur][0], b[cur][1]);
                MMA16816(acc[0][2 * g + 1], ah[0][0], ah[0][1], ah[0][2], ah[0][3], b[cur][2], b[cur][3]);
                MMA16816(acc[1][2 * g],     ah[1][0], ah[1][1], ah[1][2], ah[1][3], b[cur][0], b[cur][1]);
                MMA16816(acc[1][2 * g + 1], ah[1][0], ah[1][1], ah[1][2], ah[1][3], b[cur][2], b[cur][3]);
            }
        }
    }

    // ================= epilogue: bias + ReLU + LN =================
    float* ssum = (float*)(smem + OFF_SSUM);
    float* sssq = (float*)(smem + OFF_SSSQ);
    float* rst  = (float*)(smem + OFF_RST);

#pragma unroll
    for (int mt = 0; mt < 2; mt++) {
        float sum0 = 0.f, ssq0 = 0.f, sum1 = 0.f, ssq1 = 0.f;
#pragma unroll
        for (int t = 0; t < 8; t++) {
            int cb = wn * 64 + t * 8 + (lane & 3) * 2;
            float b0v = bias_s[cb], b1v = bias_s[cb + 1];
            float h;
            h = fmaxf(acc[mt][t][0] + b0v, 0.f); acc[mt][t][0] = h; sum0 += h; ssq0 += h * h;
            h = fmaxf(acc[mt][t][1] + b1v, 0.f); acc[mt][t][1] = h; sum0 += h; ssq0 += h * h;
            h = fmaxf(acc[mt][t][2] + b0v, 0.f); acc[mt][t][2] = h; sum1 += h; ssq1 += h * h;
            h = fmaxf(acc[mt][t][3] + b1v, 0.f); acc[mt][t][3] = h; sum1 += h; ssq1 += h * h;
        }
#pragma unroll
        for (int o = 1; o <= 2; o <<= 1) {
            sum0 += __shfl_xor_sync(0xffffffffu, sum0, o);
            ssq0 += __shfl_xor_sync(0xffffffffu, ssq0, o);
            sum1 += __shfl_xor_sync(0xffffffffu, sum1, o);
            ssq1 += __shfl_xor_sync(0xffffffffu, ssq1, o);
        }
        if ((lane & 3) == 0) {
            int r0 = wm * 32 + mt * 16 + (lane >> 2);
            ssum[r0 * 8 + wn] = sum0;       sssq[r0 * 8 + wn] = ssq0;
            ssum[(r0 + 8) * 8 + wn] = sum1; sssq[(r0 + 8) * 8 + wn] = ssq1;
        }
    }
    __syncthreads();
    if (tid < 64) {
        float s = 0.f, q = 0.f;
#pragma unroll
        for (int i = 0; i < 8; i++) { s += ssum[tid * 8 + i]; q += sssq[tid * 8 + i]; }
        float mean = s * (1.f / 512.f);
        float var  = q * (1.f / 512.f) - mean * mean;
        rst[tid * 2] = mean;
        rst[tid * 2 + 1] = rsqrtf(var + 1e-5f);
    }
    __syncthreads();

#pragma unroll
    for (int mt = 0; mt < 2; mt++) {
        int r0 = wm * 32 + mt * 16 + (lane >> 2);
        float m0 = rst[r0 * 2], rs0 = rst[r0 * 2 + 1];
        float m1 = rst[(r0 + 8) * 2], rs1 = rst[(r0 + 8) * 2 + 1];
        int gr0 = row0 + r0, gr1 = gr0 + 8;
        int b0i = gr0 / KSPLIT, j0 = gr0 - b0i * KSPLIT;
        int b1i = gr1 / KSPLIT, j1 = gr1 - b1i * KSPLIT;
        float* o0 = out + ((size_t)b0i * NQ + QOFF + j0) * 512;
        float* o1 = out + ((size_t)b1i * NQ + QOFF + j1) * 512;
#pragma unroll
        for (int t = 0; t < 8; t++) {
            int cb = wn * 64 + t * 8 + (lane & 3) * 2;
            float g0 = gam_s[cb], g1 = gam_s[cb + 1];
            float e0 = bet_s[cb], e1 = bet_s[cb + 1];
            float2 v0 = make_float2((acc[mt][t][0] - m0) * rs0 * g0 + e0,
                                    (acc[mt][t][1] - m0) * rs0 * g1 + e1);
            float2 v1 = make_float2((acc[mt][t][2] - m1) * rs1 * g0 + e0,
                                    (acc[mt][t][3] - m1) * rs1 * g1 + e1);
            *(float2*)(o0 + cb) = v0;
            *(float2*)(o1 + cb) = v1;
        }
    }
}

__global__ void __launch_bounds__(THREADS, 1)
fused_kernel(const float* __restrict__ x,
             const float* b0, const float* g0, const float* be0,
             const float* b1, const float* g1, const float* be1,
             const float* b2, const float* g2, const float* be2,
             float* __restrict__ out) {
    const int blk = blockIdx.x;
    if (blk < 32)         run_split<1,  400, 7, 0,     0 >(x, b0, g0, be0, out, g_w0, blk);
    else if (blk < 1952)  run_split<60, 256, 4, 400,   1 >(x, b1, g1, be1, out, g_w1, blk - 32);
    else                  run_split<36, 256, 4, 15760, 61>(x, b2, g2, be2, out, g_w2, blk - 1952);
}

// ================= weight prep: W f32 -> fp16 (zero-padded) =================
__device__ __forceinline__ void prep_one(const float* __restrict__ W, uint4* wp,
                                         int Lvalid, int idx) {
    int k = idx >> 9, n = idx & 511;
    float v = (k < Lvalid) ? W[(size_t)k * 512 + n] : 0.f;
    __half h = __float2half_rn(v);
    ((uint16_t*)wp)[idx] = *(uint16_t*)&h;
}

__global__ void prep_kernel(const float* __restrict__ W0, const float* __restrict__ W1,
                            const float* __restrict__ W2) {
    const int idx = blockIdx.x * blockDim.x + threadIdx.x;
    const int T0 = 448 * 512, T1 = 256 * 512, T2 = 256 * 512;
    if (idx < T0)                prep_one(W0, g_w0, 400, idx);
    else if (idx < T0 + T1)      prep_one(W1, g_w1, 256, idx - T0);
    else if (idx < T0 + T1 + T2) prep_one(W2, g_w2, 256, idx - T0 - T1);
}

// ================= launch =================
extern "C" void kernel_launch(void* const* d_in, const int* in_sizes, int n_in,
                              void* d_out, int out_size) {
    (void)in_sizes; (void)n_in; (void)out_size;
    const float* x = (const float*)d_in[0];
    float* out = (float*)d_out;

    cudaFuncSetAttribute(fused_kernel, cudaFuncAttributeMaxDynamicSharedMemorySize, SMEM_TOTAL);

    const int prep_total = (448 + 256 + 256) * 512;
    prep_kernel<<<(prep_total + 255) / 256, 256>>>(
        (const float*)d_in[1], (const float*)d_in[5], (const float*)d_in[9]);

    fused_kernel<<<3104, THREADS, SMEM_TOTAL>>>(
        x,
        (const float*)d_in[2],  (const float*)d_in[3],  (const float*)d_in[4],
        (const float*)d_in[6],  (const float*)d_in[7],  (const float*)d_in[8],
        (const float*)d_in[10], (const float*)d_in[11], (const float*)d_in[12],
        out);
}

// round 10
// speedup vs baseline: 3.2353x; 1.0995x over previous
#include <cuda_runtime.h>
#include <cuda_fp16.h>
#include <cstdint>

#define TOTAL_DIM 24976
#define NQ        97
#define THREADS   512

// ---- dynamic SMEM layout (bytes) ---- (B no longer lives in smem!)
#define OFF_BIAS  0
#define OFF_GAMMA 2048
#define OFF_BETA  4096
#define OFF_SSUM  6144     // [64][8] f32
#define OFF_SSSQ  8192     // [64][8] f32
#define OFF_RST   10240    // [64][2] f32
#define OFF_A     10752    // 2 stages x 64 rows x 144B (single fp16 plane)
#define A_STAGE   9216
#define A_ROWB    144
#define SMEM_TOTAL 29184

// ---- prepped weights in MMA FRAGMENT layout ----
// uint4 index: cks*1024 + j*32 + lane   (cks = c*4+ks, j = n16-group 0..31)
// lane's uint4 = {b0,b1,b2,b3}: b0 = W[k0..k0+1][nv], b1 = +8k, b2 = +8n, b3 = +8k+8n
// with k0 = 16*cks + (lane&3)*2, nv = j*16 + (lane>>2).
__device__ uint4 g_w0[448 * 512 / 8];
__device__ uint4 g_w1[256 * 512 / 8];
__device__ uint4 g_w2[256 * 512 / 8];

__device__ __forceinline__ uint32_t smem_u32(const void* p) {
    uint32_t a;
    asm("{ .reg .u64 t; cvta.to.shared.u64 t, %1; cvt.u32.u64 %0, t; }" : "=r"(a) : "l"(p));
    return a;
}
#define LDSM_X4(r0, r1, r2, r3, a) \
    asm volatile("ldmatrix.sync.aligned.m8n8.x4.shared.b16 {%0,%1,%2,%3}, [%4];" \
                 : "=r"(r0), "=r"(r1), "=r"(r2), "=r"(r3) : "r"(a))
#define MMA16816(c, a0, a1, a2, a3, b0, b1) \
    asm volatile("mma.sync.aligned.m16n8k16.row.col.f32.f16.f16.f32 " \
                 "{%0,%1,%2,%3}, {%4,%5,%6,%7}, {%8,%9}, {%0,%1,%2,%3};" \
                 : "+f"((c)[0]), "+f"((c)[1]), "+f"((c)[2]), "+f"((c)[3]) \
                 : "r"(a0), "r"(a1), "r"(a2), "r"(a3), "r"(b0), "r"(b1))

// ================= fused GEMM + bias + ReLU + LayerNorm =================
// CTA: 64 rows x 512 cols, 16 warps, warp tile 32 x 64 (wm = wid&1, wn = wid>>1). BK = 64.
// B fragments stream from global (L1/L2-hot), A through smem.
template <int KSPLIT, int LVALID, int NCHUNK, int SEGOFF, int QOFF>
__device__ __forceinline__ void run_split(const float* __restrict__ x,
                                          const float* __restrict__ bias_g,
                                          const float* __restrict__ gamma_g,
                                          const float* __restrict__ beta_g,
                                          float* __restrict__ out,
                                          const uint4* __restrict__ wfrag,
                                          int tile) {
    extern __shared__ char smem[];
    const uint32_t sb = smem_u32(smem);
    const int tid = threadIdx.x, lane = tid & 31, wid = tid >> 5;
    const int wm = wid & 1;        // row half: rows wm*32..+32
    const int wn = wid >> 1;       // col group: cols wn*64..+64
    const int row0 = tile * 64;

    float* bias_s = (float*)(smem + OFF_BIAS);
    float* gam_s  = (float*)(smem + OFF_GAMMA);
    float* bet_s  = (float*)(smem + OFF_BETA);
    for (int i = tid; i < 512; i += THREADS) {
        bias_s[i] = bias_g[i]; gam_s[i] = gamma_g[i]; bet_s[i] = beta_g[i];
    }

    // per-thread x mapping: one row (tid>>3), two float4 slots (tid&7, +32 halfs)
    const int xrow = tid >> 3, xf4 = tid & 7;
    const float* px;
    {
        int gr = row0 + xrow;
        int bb = gr / KSPLIT, jj = gr - bb * KSPLIT;
        px = x + (size_t)bb * TOTAL_DIM + SEGOFF + (size_t)jj * LVALID + xf4 * 4;
    }

    float acc[2][8][4];
#pragma unroll
    for (int mt = 0; mt < 2; mt++)
#pragma unroll
        for (int t = 0; t < 8; t++)
#pragma unroll
            for (int c = 0; c < 4; c++) acc[mt][t][c] = 0.f;

    // B fragment base pointer for this warp/lane
    const uint4* bq = wfrag + (size_t)(wn * 4) * 32 + lane;

    float4 xv[2];
#pragma unroll
    for (int sl = 0; sl < 2; sl++) {
        int k0 = xf4 * 4 + sl * 32;
        xv[sl] = (LVALID % 64 == 0 || k0 + 4 <= LVALID) ? *(const float4*)(px + sl * 32)
                                                        : make_float4(0.f, 0.f, 0.f, 0.f);
    }

    // prefetch B fragments for cks = 0
    uint4 bf[2][4];
#pragma unroll
    for (int g = 0; g < 4; g++) bf[0][g] = bq[g * 32];

    for (int c = 0; c < NCHUNK; c++) {
        const int s = c & 1;

        // STS A(c): round to fp16, single plane
#pragma unroll
        for (int sl = 0; sl < 2; sl++) {
            __half h0 = __float2half_rn(xv[sl].x), h1 = __float2half_rn(xv[sl].y);
            __half h2 = __float2half_rn(xv[sl].z), h3 = __float2half_rn(xv[sl].w);
            uint2 ph = make_uint2((uint32_t)*(uint16_t*)&h0 | ((uint32_t)*(uint16_t*)&h1 << 16),
                                  (uint32_t)*(uint16_t*)&h2 | ((uint32_t)*(uint16_t*)&h3 << 16));
            uint32_t off = (uint32_t)(xrow * A_ROWB + xf4 * 8 + sl * 64);
            *(uint2*)(smem + OFF_A + s * A_STAGE + off) = ph;
        }
        __syncthreads();

        // issue next chunk's x loads (latency hidden under this chunk's compute)
        if (c + 1 < NCHUNK) {
#pragma unroll
            for (int sl = 0; sl < 2; sl++) {
                int k0 = (c + 1) * 64 + xf4 * 4 + sl * 32;
                xv[sl] = (LVALID % 64 == 0 || k0 + 4 <= LVALID)
                             ? *(const float4*)(px + (c + 1) * 64 + sl * 32)
                             : make_float4(0.f, 0.f, 0.f, 0.f);
            }
        }

        // ---- compute: 4 ks x (2 A-ldsm + 4 B-LDG.128 prefetch + 16 MMA) ----
        const uint32_t aB = sb + OFF_A + s * A_STAGE;
#pragma unroll
        for (int ks = 0; ks < 4; ks++) {
            const int cb = ks & 1, nb = cb ^ 1;
            // prefetch next ks (or next chunk's ks0) B fragments
            const int ncks = (ks < 3) ? (c * 4 + ks + 1) : ((c + 1) * 4);
            if (ks < 3 || c + 1 < NCHUNK) {
#pragma unroll
                for (int g = 0; g < 4; g++) bf[nb][g] = bq[(size_t)ncks * 1024 + g * 32];
            }

            const uint32_t arow = (uint32_t)(wm * 32 + (lane & 15));
            const uint32_t acol = (uint32_t)(((lane >> 4) << 3) + ks * 16);
            uint32_t ah[2][4];
#pragma unroll
            for (int mt = 0; mt < 2; mt++) {
                uint32_t aoff = (arow + mt * 16) * A_ROWB + acol * 2;
                LDSM_X4(ah[mt][0], ah[mt][1], ah[mt][2], ah[mt][3], aB + aoff);
            }
#pragma unroll
            for (int g = 0; g < 4; g++) {
                // 4 independent accumulator chains per group
                MMA16816(acc[0][2 * g],     ah[0][0], ah[0][1], ah[0][2], ah[0][3], bf[cb][g].x, bf[cb][g].y);
                MMA16816(acc[0][2 * g + 1], ah[0][0], ah[0][1], ah[0][2], ah[0][3], bf[cb][g].z, bf[cb][g].w);
                MMA16816(acc[1][2 * g],     ah[1][0], ah[1][1], ah[1][2], ah[1][3], bf[cb][g].x, bf[cb][g].y);
                MMA16816(acc[1][2 * g + 1], ah[1][0], ah[1][1], ah[1][2], ah[1][3], bf[cb][g].z, bf[cb][g].w);
            }
        }
    }

    // ================= epilogue: bias + ReLU + LN =================
    float* ssum = (float*)(smem + OFF_SSUM);
    float* sssq = (float*)(smem + OFF_SSSQ);
    float* rst  = (float*)(smem + OFF_RST);

#pragma unroll
    for (int mt = 0; mt < 2; mt++) {
        float sum0 = 0.f, ssq0 = 0.f, sum1 = 0.f, ssq1 = 0.f;
#pragma unroll
        for (int t = 0; t < 8; t++) {
            int cb = wn * 64 + t * 8 + (lane & 3) * 2;
            float b0v = bias_s[cb], b1v = bias_s[cb + 1];
            float h;
            h = fmaxf(acc[mt][t][0] + b0v, 0.f); acc[mt][t][0] = h; sum0 += h; ssq0 += h * h;
            h = fmaxf(acc[mt][t][1] + b1v, 0.f); acc[mt][t][1] = h; sum0 += h; ssq0 += h * h;
            h = fmaxf(acc[mt][t][2] + b0v, 0.f); acc[mt][t][2] = h; sum1 += h; ssq1 += h * h;
            h = fmaxf(acc[mt][t][3] + b1v, 0.f); acc[mt][t][3] = h; sum1 += h; ssq1 += h * h;
        }
#pragma unroll
        for (int o = 1; o <= 2; o <<= 1) {
            sum0 += __shfl_xor_sync(0xffffffffu, sum0, o);
            ssq0 += __shfl_xor_sync(0xffffffffu, ssq0, o);
            sum1 += __shfl_xor_sync(0xffffffffu, sum1, o);
            ssq1 += __shfl_xor_sync(0xffffffffu, ssq1, o);
        }
        if ((lane & 3) == 0) {
            int r0 = wm * 32 + mt * 16 + (lane >> 2);
            ssum[r0 * 8 + wn] = sum0;       sssq[r0 * 8 + wn] = ssq0;
            ssum[(r0 + 8) * 8 + wn] = sum1; sssq[(r0 + 8) * 8 + wn] = ssq1;
        }
    }
    __syncthreads();
    if (tid < 64) {
        float s = 0.f, q = 0.f;
#pragma unroll
        for (int i = 0; i < 8; i++) { s += ssum[tid * 8 + i]; q += sssq[tid * 8 + i]; }
        float mean = s * (1.f / 512.f);
        float var  = q * (1.f / 512.f) - mean * mean;
        rst[tid * 2] = mean;
        rst[tid * 2 + 1] = rsqrtf(var + 1e-5f);
    }
    __syncthreads();

#pragma unroll
    for (int mt = 0; mt < 2; mt++) {
        int r0 = wm * 32 + mt * 16 + (lane >> 2);
        float m0 = rst[r0 * 2], rs0 = rst[r0 * 2 + 1];
        float m1 = rst[(r0 + 8) * 2], rs1 = rst[(r0 + 8) * 2 + 1];
        int gr0 = row0 + r0, gr1 = gr0 + 8;
        int b0i = gr0 / KSPLIT, j0 = gr0 - b0i * KSPLIT;
        int b1i = gr1 / KSPLIT, j1 = gr1 - b1i * KSPLIT;
        float* o0 = out + ((size_t)b0i * NQ + QOFF + j0) * 512;
        float* o1 = out + ((size_t)b1i * NQ + QOFF + j1) * 512;
#pragma unroll
        for (int t = 0; t < 8; t++) {
            int cb = wn * 64 + t * 8 + (lane & 3) * 2;
            float g0 = gam_s[cb], g1 = gam_s[cb + 1];
            float e0 = bet_s[cb], e1 = bet_s[cb + 1];
            float2 v0 = make_float2((acc[mt][t][0] - m0) * rs0 * g0 + e0,
                                    (acc[mt][t][1] - m0) * rs0 * g1 + e1);
            float2 v1 = make_float2((acc[mt][t][2] - m1) * rs1 * g0 + e0,
                                    (acc[mt][t][3] - m1) * rs1 * g1 + e1);
            *(float2*)(o0 + cb) = v0;
            *(float2*)(o1 + cb) = v1;
        }
    }
}

__global__ void __launch_bounds__(THREADS, 1)
fused_kernel(const float* __restrict__ x,
             const float* b0, const float* g0, const float* be0,
             const float* b1, const float* g1, const float* be1,
             const float* b2, const float* g2, const float* be2,
             float* __restrict__ out) {
    const int blk = blockIdx.x;
    if (blk < 32)         run_split<1,  400, 7, 0,     0 >(x, b0, g0, be0, out, g_w0, blk);
    else if (blk < 1952)  run_split<60, 256, 4, 400,   1 >(x, b1, g1, be1, out, g_w1, blk - 32);
    else                  run_split<36, 256, 4, 15760, 61>(x, b2, g2, be2, out, g_w2, blk - 1952);
}

// ================= weight prep: W f32 -> fp16 MMA-fragment layout =================
__device__ __forceinline__ uint32_t rdh(const float* __restrict__ W, int Lvalid, int k, int n) {
    float v = (k < Lvalid) ? W[(size_t)k * 512 + n] : 0.f;
    __half h = __float2half_rn(v);
    return (uint32_t)*(uint16_t*)&h;
}
__device__ __forceinline__ void prep_frag(const float* __restrict__ W, uint4* dst,
                                          int Lvalid, int t) {
    int lane = t & 31;
    int j    = (t >> 5) & 31;       // n16-group
    int cks  = t >> 10;             // c*4 + ks
    int k0   = cks * 16 + (lane & 3) * 2;
    int nv   = j * 16 + (lane >> 2);
    uint4 o;
    o.x = rdh(W, Lvalid, k0,     nv)     | (rdh(W, Lvalid, k0 + 1, nv)     << 16);
    o.y = rdh(W, Lvalid, k0 + 8, nv)     | (rdh(W, Lvalid, k0 + 9, nv)     << 16);
    o.z = rdh(W, Lvalid, k0,     nv + 8) | (rdh(W, Lvalid, k0 + 1, nv + 8) << 16);
    o.w = rdh(W, Lvalid, k0 + 8, nv + 8) | (rdh(W, Lvalid, k0 + 9, nv + 8) << 16);
    dst[t] = o;
}

__global__ void prep_kernel(const float* __restrict__ W0, const float* __restrict__ W1,
                            const float* __restrict__ W2) {
    const int idx = blockIdx.x * blockDim.x + threadIdx.x;
    const int T0 = 448 * 512 / 8, T1 = 256 * 512 / 8, T2 = 256 * 512 / 8;
    if (idx < T0)                prep_frag(W0, g_w0, 400, idx);
    else if (idx < T0 + T1)      prep_frag(W1, g_w1, 256, idx - T0);
    else if (idx < T0 + T1 + T2) prep_frag(W2, g_w2, 256, idx - T0 - T1);
}

// ================= launch =================
extern "C" void kernel_launch(void* const* d_in, const int* in_sizes, int n_in,
                              void* d_out, int out_size) {
    (void)in_sizes; (void)n_in; (void)out_size;
    const float* x = (const float*)d_in[0];
    float* out = (float*)d_out;

    cudaFuncSetAttribute(fused_kernel, cudaFuncAttributeMaxDynamicSharedMemorySize, SMEM_TOTAL);

    const int prep_total = (448 + 256 + 256) * 512 / 8;
    prep_kernel<<<(prep_total + 255) / 256, 256>>>(
        (const float*)d_in[1], (const float*)d_in[5], (const float*)d_in[9]);

    fused_kernel<<<3104, THREADS, SMEM_TOTAL>>>(
        x,
        (const float*)d_in[2],  (const float*)d_in[3],  (const float*)d_in[4],
        (const float*)d_in[6],  (const float*)d_in[7],  (const float*)d_in[8],
        (const float*)d_in[10], (const float*)d_in[11], (const float*)d_in[12],
        out);
}

// round 11
// speedup vs baseline: 3.3529x; 1.0364x over previous
#include <cuda_runtime.h>
#include <cuda_fp16.h>
#include <cstdint>

#define TOTAL_DIM 24976
#define NQ        97
#define THREADS   256

// ---- dynamic SMEM layout (bytes) ----
#define OFF_BIAS  0
#define OFF_GAMMA 2048
#define OFF_BETA  4096
#define OFF_SSUM  6144     // [32][8] f32
#define OFF_SSSQ  7168     // [32][8] f32
#define OFF_RST   8192     // [32][2] f32
#define OFF_A     8448     // 2 stages x 32 rows x 144B (single fp16 plane)
#define A_STAGE   4608
#define A_ROWB    144
#define SMEM_TOTAL 17664

// ---- prepped weights in MMA FRAGMENT layout ----
// uint4 index: cks*1024 + j*32 + lane   (cks = c*4+ks, j = n16-group 0..31)
__device__ uint4 g_w0[448 * 512 / 8];
__device__ uint4 g_w1[256 * 512 / 8];
__device__ uint4 g_w2[256 * 512 / 8];

__device__ __forceinline__ uint32_t smem_u32(const void* p) {
    uint32_t a;
    asm("{ .reg .u64 t; cvta.to.shared.u64 t, %1; cvt.u32.u64 %0, t; }" : "=r"(a) : "l"(p));
    return a;
}
#define LDSM_X4(r0, r1, r2, r3, a) \
    asm volatile("ldmatrix.sync.aligned.m8n8.x4.shared.b16 {%0,%1,%2,%3}, [%4];" \
                 : "=r"(r0), "=r"(r1), "=r"(r2), "=r"(r3) : "r"(a))
#define MMA16816(c, a0, a1, a2, a3, b0, b1) \
    asm volatile("mma.sync.aligned.m16n8k16.row.col.f32.f16.f16.f32 " \
                 "{%0,%1,%2,%3}, {%4,%5,%6,%7}, {%8,%9}, {%0,%1,%2,%3};" \
                 : "+f"((c)[0]), "+f"((c)[1]), "+f"((c)[2]), "+f"((c)[3]) \
                 : "r"(a0), "r"(a1), "r"(a2), "r"(a3), "r"(b0), "r"(b1))

// ================= fused GEMM + bias + ReLU + LayerNorm =================
// CTA: 32 rows x 512 cols, 8 warps, warp tile 32 x 64 (wn = wid). BK = 64.
// 2 CTAs/SM co-resident; B fragments stream from global (L1/L2-hot), A via smem.
template <int KSPLIT, int LVALID, int NCHUNK, int SEGOFF, int QOFF>
__device__ __forceinline__ void run_split(const float* __restrict__ x,
                                          const float* __restrict__ bias_g,
                                          const float* __restrict__ gamma_g,
                                          const float* __restrict__ beta_g,
                                          float* __restrict__ out,
                                          const uint4* __restrict__ wfrag,
                                          int tile) {
    extern __shared__ char smem[];
    const uint32_t sb = smem_u32(smem);
    const int tid = threadIdx.x, lane = tid & 31, wn = tid >> 5;
    const int row0 = tile * 32;

    float* bias_s = (float*)(smem + OFF_BIAS);
    float* gam_s  = (float*)(smem + OFF_GAMMA);
    float* bet_s  = (float*)(smem + OFF_BETA);
    for (int i = tid; i < 512; i += THREADS) {
        bias_s[i] = bias_g[i]; gam_s[i] = gamma_g[i]; bet_s[i] = beta_g[i];
    }

    // per-thread x mapping: one row (tid>>3, 0..31), two float4 slots (tid&7, +32 halfs)
    const int xrow = tid >> 3, xf4 = tid & 7;
    const float* px;
    {
        int gr = row0 + xrow;
        int bb = gr / KSPLIT, jj = gr - bb * KSPLIT;
        px = x + (size_t)bb * TOTAL_DIM + SEGOFF + (size_t)jj * LVALID + xf4 * 4;
    }

    float acc[2][8][4];
#pragma unroll
    for (int mt = 0; mt < 2; mt++)
#pragma unroll
        for (int t = 0; t < 8; t++)
#pragma unroll
            for (int c = 0; c < 4; c++) acc[mt][t][c] = 0.f;

    // B fragment base pointer for this warp/lane
    const uint4* bq = wfrag + (size_t)(wn * 4) * 32 + lane;

    float4 xv[2];
#pragma unroll
    for (int sl = 0; sl < 2; sl++) {
        int k0 = xf4 * 4 + sl * 32;
        xv[sl] = (LVALID % 64 == 0 || k0 + 4 <= LVALID) ? *(const float4*)(px + sl * 32)
                                                        : make_float4(0.f, 0.f, 0.f, 0.f);
    }

    // prefetch B fragments for cks = 0
    uint4 bf[2][4];
#pragma unroll
    for (int g = 0; g < 4; g++) bf[0][g] = bq[g * 32];

    for (int c = 0; c < NCHUNK; c++) {
        const int s = c & 1;

        // STS A(c): round to fp16, single plane
#pragma unroll
        for (int sl = 0; sl < 2; sl++) {
            __half h0 = __float2half_rn(xv[sl].x), h1 = __float2half_rn(xv[sl].y);
            __half h2 = __float2half_rn(xv[sl].z), h3 = __float2half_rn(xv[sl].w);
            uint2 ph = make_uint2((uint32_t)*(uint16_t*)&h0 | ((uint32_t)*(uint16_t*)&h1 << 16),
                                  (uint32_t)*(uint16_t*)&h2 | ((uint32_t)*(uint16_t*)&h3 << 16));
            uint32_t off = (uint32_t)(xrow * A_ROWB + xf4 * 8 + sl * 64);
            *(uint2*)(smem + OFF_A + s * A_STAGE + off) = ph;
        }
        __syncthreads();

        // issue next chunk's x loads (latency hidden under this chunk's compute)
        if (c + 1 < NCHUNK) {
#pragma unroll
            for (int sl = 0; sl < 2; sl++) {
                int k0 = (c + 1) * 64 + xf4 * 4 + sl * 32;
                xv[sl] = (LVALID % 64 == 0 || k0 + 4 <= LVALID)
                             ? *(const float4*)(px + (c + 1) * 64 + sl * 32)
                             : make_float4(0.f, 0.f, 0.f, 0.f);
            }
        }

        // ---- compute: 4 ks x (2 A-ldsm + 4 B-LDG.128 prefetch + 16 MMA) ----
        const uint32_t aB = sb + OFF_A + s * A_STAGE;
#pragma unroll
        for (int ks = 0; ks < 4; ks++) {
            const int cb = ks & 1, nb = cb ^ 1;
            // prefetch next ks (or next chunk's ks0) B fragments
            const int ncks = (ks < 3) ? (c * 4 + ks + 1) : ((c + 1) * 4);
            if (ks < 3 || c + 1 < NCHUNK) {
#pragma unroll
                for (int g = 0; g < 4; g++) bf[nb][g] = bq[(size_t)ncks * 1024 + g * 32];
            }

            const uint32_t arow = (uint32_t)(lane & 15);
            const uint32_t acol = (uint32_t)(((lane >> 4) << 3) + ks * 16);
            uint32_t ah[2][4];
#pragma unroll
            for (int mt = 0; mt < 2; mt++) {
                uint32_t aoff = (arow + mt * 16) * A_ROWB + acol * 2;
                LDSM_X4(ah[mt][0], ah[mt][1], ah[mt][2], ah[mt][3], aB + aoff);
            }
#pragma unroll
            for (int g = 0; g < 4; g++) {
                // 4 independent accumulator chains per group
                MMA16816(acc[0][2 * g],     ah[0][0], ah[0][1], ah[0][2], ah[0][3], bf[cb][g].x, bf[cb][g].y);
                MMA16816(acc[0][2 * g + 1], ah[0][0], ah[0][1], ah[0][2], ah[0][3], bf[cb][g].z, bf[cb][g].w);
                MMA16816(acc[1][2 * g],     ah[1][0], ah[1][1], ah[1][2], ah[1][3], bf[cb][g].x, bf[cb][g].y);
                MMA16816(acc[1][2 * g + 1], ah[1][0], ah[1][1], ah[1][2], ah[1][3], bf[cb][g].z, bf[cb][g].w);
            }
        }
    }

    // ================= epilogue: bias + ReLU + LN =================
    float* ssum = (float*)(smem + OFF_SSUM);
    float* sssq = (float*)(smem + OFF_SSSQ);
    float* rst  = (float*)(smem + OFF_RST);

#pragma unroll
    for (int mt = 0; mt < 2; mt++) {
        float sum0 = 0.f, ssq0 = 0.f, sum1 = 0.f, ssq1 = 0.f;
#pragma unroll
        for (int t = 0; t < 8; t++) {
            int cb = wn * 64 + t * 8 + (lane & 3) * 2;
            float b0v = bias_s[cb], b1v = bias_s[cb + 1];
            float h;
            h = fmaxf(acc[mt][t][0] + b0v, 0.f); acc[mt][t][0] = h; sum0 += h; ssq0 += h * h;
            h = fmaxf(acc[mt][t][1] + b1v, 0.f); acc[mt][t][1] = h; sum0 += h; ssq0 += h * h;
            h = fmaxf(acc[mt][t][2] + b0v, 0.f); acc[mt][t][2] = h; sum1 += h; ssq1 += h * h;
            h = fmaxf(acc[mt][t][3] + b1v, 0.f); acc[mt][t][3] = h; sum1 += h; ssq1 += h * h;
        }
#pragma unroll
        for (int o = 1; o <= 2; o <<= 1) {
            sum0 += __shfl_xor_sync(0xffffffffu, sum0, o);
            ssq0 += __shfl_xor_sync(0xffffffffu, ssq0, o);
            sum1 += __shfl_xor_sync(0xffffffffu, sum1, o);
            ssq1 += __shfl_xor_sync(0xffffffffu, ssq1, o);
        }
        if ((lane & 3) == 0) {
            int r0 = mt * 16 + (lane >> 2);
            ssum[r0 * 8 + wn] = sum0;       sssq[r0 * 8 + wn] = ssq0;
            ssum[(r0 + 8) * 8 + wn] = sum1; sssq[(r0 + 8) * 8 + wn] = ssq1;
        }
    }
    __syncthreads();
    if (tid < 32) {
        float s = 0.f, q = 0.f;
#pragma unroll
        for (int i = 0; i < 8; i++) { s += ssum[tid * 8 + i]; q += sssq[tid * 8 + i]; }
        float mean = s * (1.f / 512.f);
        float var  = q * (1.f / 512.f) - mean * mean;
        rst[tid * 2] = mean;
        rst[tid * 2 + 1] = rsqrtf(var + 1e-5f);
    }
    __syncthreads();

#pragma unroll
    for (int mt = 0; mt < 2; mt++) {
        int r0 = mt * 16 + (lane >> 2);
        float m0 = rst[r0 * 2], rs0 = rst[r0 * 2 + 1];
        float m1 = rst[(r0 + 8) * 2], rs1 = rst[(r0 + 8) * 2 + 1];
        int gr0 = row0 + r0, gr1 = gr0 + 8;
        int b0i = gr0 / KSPLIT, j0 = gr0 - b0i * KSPLIT;
        int b1i = gr1 / KSPLIT, j1 = gr1 - b1i * KSPLIT;
        float* o0 = out + ((size_t)b0i * NQ + QOFF + j0) * 512;
        float* o1 = out + ((size_t)b1i * NQ + QOFF + j1) * 512;
#pragma unroll
        for (int t = 0; t < 8; t++) {
            int cb = wn * 64 + t * 8 + (lane & 3) * 2;
            float g0 = gam_s[cb], g1 = gam_s[cb + 1];
            float e0 = bet_s[cb], e1 = bet_s[cb + 1];
            float2 v0 = make_float2((acc[mt][t][0] - m0) * rs0 * g0 + e0,
                                    (acc[mt][t][1] - m0) * rs0 * g1 + e1);
            float2 v1 = make_float2((acc[mt][t][2] - m1) * rs1 * g0 + e0,
                                    (acc[mt][t][3] - m1) * rs1 * g1 + e1);
            *(float2*)(o0 + cb) = v0;
            *(float2*)(o1 + cb) = v1;
        }
    }
}

__global__ void __launch_bounds__(THREADS, 2)
fused_kernel(const float* __restrict__ x,
             const float* b0, const float* g0, const float* be0,
             const float* b1, const float* g1, const float* be1,
             const float* b2, const float* g2, const float* be2,
             float* __restrict__ out) {
    const int blk = blockIdx.x;
    if (blk < 64)         run_split<1,  400, 7, 0,     0 >(x, b0, g0, be0, out, g_w0, blk);
    else if (blk < 3904)  run_split<60, 256, 4, 400,   1 >(x, b1, g1, be1, out, g_w1, blk - 64);
    else                  run_split<36, 256, 4, 15760, 61>(x, b2, g2, be2, out, g_w2, blk - 3904);
}

// ================= weight prep: W f32 -> fp16 MMA-fragment layout =================
__device__ __forceinline__ uint32_t rdh(const float* __restrict__ W, int Lvalid, int k, int n) {
    float v = (k < Lvalid) ? W[(size_t)k * 512 + n] : 0.f;
    __half h = __float2half_rn(v);
    return (uint32_t)*(uint16_t*)&h;
}
__device__ __forceinline__ void prep_frag(const float* __restrict__ W, uint4* dst,
                                          int Lvalid, int t) {
    int lane = t & 31;
    int j    = (t >> 5) & 31;       // n16-group
    int cks  = t >> 10;             // c*4 + ks
    int k0   = cks * 16 + (lane & 3) * 2;
    int nv   = j * 16 + (lane >> 2);
    uint4 o;
    o.x = rdh(W, Lvalid, k0,     nv)     | (rdh(W, Lvalid, k0 + 1, nv)     << 16);
    o.y = rdh(W, Lvalid, k0 + 8, nv)     | (rdh(W, Lvalid, k0 + 9, nv)     << 16);
    o.z = rdh(W, Lvalid, k0,     nv + 8) | (rdh(W, Lvalid, k0 + 1, nv + 8) << 16);
    o.w = rdh(W, Lvalid, k0 + 8, nv + 8) | (rdh(W, Lvalid, k0 + 9, nv + 8) << 16);
    dst[t] = o;
}

__global__ void prep_kernel(const float* __restrict__ W0, const float* __restrict__ W1,
                            const float* __restrict__ W2) {
    const int idx = blockIdx.x * blockDim.x + threadIdx.x;
    const int T0 = 448 * 512 / 8, T1 = 256 * 512 / 8, T2 = 256 * 512 / 8;
    if (idx < T0)                prep_frag(W0, g_w0, 400, idx);
    else if (idx < T0 + T1)      prep_frag(W1, g_w1, 256, idx - T0);
    else if (idx < T0 + T1 + T2) prep_frag(W2, g_w2, 256, idx - T0 - T1);
}

// ================= launch =================
extern "C" void kernel_launch(void* const* d_in, const int* in_sizes, int n_in,
                              void* d_out, int out_size) {
    (void)in_sizes; (void)n_in; (void)out_size;
    const float* x = (const float*)d_in[0];
    float* out = (float*)d_out;

    cudaFuncSetAttribute(fused_kernel, cudaFuncAttributeMaxDynamicSharedMemorySize, SMEM_TOTAL);

    const int prep_total = (448 + 256 + 256) * 512 / 8;
    prep_kernel<<<(prep_total + 255) / 256, 256>>>(
        (const float*)d_in[1], (const float*)d_in[5], (const float*)d_in[9]);

    fused_kernel<<<6208, THREADS, SMEM_TOTAL>>>(
        x,
        (const float*)d_in[2],  (const float*)d_in[3],  (const float*)d_in[4],
        (const float*)d_in[6],  (const float*)d_in[7],  (const float*)d_in[8],
        (const float*)d_in[10], (const float*)d_in[11], (const float*)d_in[12],
        out);
}

// round 12
// speedup vs baseline: 3.5283x; 1.0523x over previous
#include <cuda_runtime.h>
#include <cuda_fp16.h>
#include <cstdint>

#define TOTAL_DIM 24976
#define NQ        97
#define THREADS   256

// ---- dynamic SMEM layout (bytes) ----
#define OFF_BIAS  0
#define OFF_GAMMA 2048
#define OFF_BETA  4096
#define OFF_SSUM  6144     // [32][8] f32
#define OFF_SSSQ  7168     // [32][8] f32
#define OFF_RST   8192     // [32][2] f32
#define OFF_A     8448     // 2 stages x 32 rows x 144B (single fp16 plane)
#define A_STAGE   4608
#define A_ROWB    144
#define SMEM_TOTAL 17664

// ---- prepped weights in MMA FRAGMENT layout ----
// uint4 index: cks*1024 + j*32 + lane   (cks = c*4+ks, j = n16-group 0..31)
__device__ uint4 g_w0[448 * 512 / 8];
__device__ uint4 g_w1[256 * 512 / 8];
__device__ uint4 g_w2[256 * 512 / 8];

__device__ __forceinline__ uint32_t smem_u32(const void* p) {
    uint32_t a;
    asm("{ .reg .u64 t; cvta.to.shared.u64 t, %1; cvt.u32.u64 %0, t; }" : "=r"(a) : "l"(p));
    return a;
}
#define LDSM_X4(r0, r1, r2, r3, a) \
    asm volatile("ldmatrix.sync.aligned.m8n8.x4.shared.b16 {%0,%1,%2,%3}, [%4];" \
                 : "=r"(r0), "=r"(r1), "=r"(r2), "=r"(r3) : "r"(a))
#define MMA16816(c, a0, a1, a2, a3, b0, b1) \
    asm volatile("mma.sync.aligned.m16n8k16.row.col.f32.f16.f16.f32 " \
                 "{%0,%1,%2,%3}, {%4,%5,%6,%7}, {%8,%9}, {%0,%1,%2,%3};" \
                 : "+f"((c)[0]), "+f"((c)[1]), "+f"((c)[2]), "+f"((c)[3]) \
                 : "r"(a0), "r"(a1), "r"(a2), "r"(a3), "r"(b0), "r"(b1))

// ================= fused GEMM + bias + ReLU + LayerNorm =================
// CTA: 32 rows x 512 cols, 8 warps, warp tile 32 x 64 (wn = wid). BK = 64.
// 2 CTAs/SM; B fragments stream from global (L1/L2-hot), A via smem.
// Both A-ldsm and B-LDG are software-pipelined one ks ahead.
template <int KSPLIT, int LVALID, int NCHUNK, int SEGOFF, int QOFF>
__device__ __forceinline__ void run_split(const float* __restrict__ x,
                                          const float* __restrict__ bias_g,
                                          const float* __restrict__ gamma_g,
                                          const float* __restrict__ beta_g,
                                          float* __restrict__ out,
                                          const uint4* __restrict__ wfrag,
                                          int tile) {
    extern __shared__ char smem[];
    const uint32_t sb = smem_u32(smem);
    const int tid = threadIdx.x, lane = tid & 31, wn = tid >> 5;
    const int row0 = tile * 32;

    float* bias_s = (float*)(smem + OFF_BIAS);
    float* gam_s  = (float*)(smem + OFF_GAMMA);
    float* bet_s  = (float*)(smem + OFF_BETA);
    for (int i = tid; i < 512; i += THREADS) {
        bias_s[i] = bias_g[i]; gam_s[i] = gamma_g[i]; bet_s[i] = beta_g[i];
    }

    // per-thread x mapping: one row (tid>>3, 0..31), two float4 slots (tid&7, +32 halfs)
    const int xrow = tid >> 3, xf4 = tid & 7;
    const float* px;
    {
        int gr = row0 + xrow;
        int bb = gr / KSPLIT, jj = gr - bb * KSPLIT;
        px = x + (size_t)bb * TOTAL_DIM + SEGOFF + (size_t)jj * LVALID + xf4 * 4;
    }

    float acc[2][8][4];
#pragma unroll
    for (int mt = 0; mt < 2; mt++)
#pragma unroll
        for (int t = 0; t < 8; t++)
#pragma unroll
            for (int c = 0; c < 4; c++) acc[mt][t][c] = 0.f;

    // B fragment base pointer for this warp/lane
    const uint4* bq = wfrag + (size_t)(wn * 4) * 32 + lane;

    float4 xv[2];
#pragma unroll
    for (int sl = 0; sl < 2; sl++) {
        int k0 = xf4 * 4 + sl * 32;
        xv[sl] = (LVALID % 64 == 0 || k0 + 4 <= LVALID) ? *(const float4*)(px + sl * 32)
                                                        : make_float4(0.f, 0.f, 0.f, 0.f);
    }

    // prefetch B fragments for cks = 0
    uint4 bf[2][4];
#pragma unroll
    for (int g = 0; g < 4; g++) bf[0][g] = bq[g * 32];

    // A-ldsm lane addressing (constant across ks)
    const uint32_t arow = (uint32_t)(lane & 15);
    const uint32_t acolb = (uint32_t)(((lane >> 4) << 3) * 2);   // byte offset of 8-col group

    for (int c = 0; c < NCHUNK; c++) {
        const int s = c & 1;

        // STS A(c): round to fp16, single plane
#pragma unroll
        for (int sl = 0; sl < 2; sl++) {
            __half h0 = __float2half_rn(xv[sl].x), h1 = __float2half_rn(xv[sl].y);
            __half h2 = __float2half_rn(xv[sl].z), h3 = __float2half_rn(xv[sl].w);
            uint2 ph = make_uint2((uint32_t)*(uint16_t*)&h0 | ((uint32_t)*(uint16_t*)&h1 << 16),
                                  (uint32_t)*(uint16_t*)&h2 | ((uint32_t)*(uint16_t*)&h3 << 16));
            uint32_t off = (uint32_t)(xrow * A_ROWB + xf4 * 8 + sl * 64);
            *(uint2*)(smem + OFF_A + s * A_STAGE + off) = ph;
        }
        __syncthreads();

        // issue next chunk's x loads (latency hidden under this chunk's compute)
        if (c + 1 < NCHUNK) {
#pragma unroll
            for (int sl = 0; sl < 2; sl++) {
                int k0 = (c + 1) * 64 + xf4 * 4 + sl * 32;
                xv[sl] = (LVALID % 64 == 0 || k0 + 4 <= LVALID)
                             ? *(const float4*)(px + (c + 1) * 64 + sl * 32)
                             : make_float4(0.f, 0.f, 0.f, 0.f);
            }
        }

        // ---- compute: ks loop with A-ldsm and B-LDG both pipelined 1 ks ahead ----
        const uint32_t aB = sb + OFF_A + s * A_STAGE;

        uint32_t ah[2][2][4];   // [buffer][mt][4]
        // prime A for ks=0 of this chunk
#pragma unroll
        for (int mt = 0; mt < 2; mt++) {
            uint32_t aoff = (arow + mt * 16) * A_ROWB + acolb;
            LDSM_X4(ah[0][mt][0], ah[0][mt][1], ah[0][mt][2], ah[0][mt][3], aB + aoff);
        }

#pragma unroll
        for (int ks = 0; ks < 4; ks++) {
            const int cb = ks & 1, nb = cb ^ 1;
            // prefetch next ks (or next chunk's ks0) B fragments
            const int ncks = (ks < 3) ? (c * 4 + ks + 1) : ((c + 1) * 4);
            if (ks < 3 || c + 1 < NCHUNK) {
#pragma unroll
                for (int g = 0; g < 4; g++) bf[nb][g] = bq[(size_t)ncks * 1024 + g * 32];
            }
            // prefetch next ks A fragments (same chunk/stage only)
            if (ks < 3) {
#pragma unroll
                for (int mt = 0; mt < 2; mt++) {
                    uint32_t aoff = (arow + mt * 16) * A_ROWB + acolb + (uint32_t)(ks + 1) * 32;
                    LDSM_X4(ah[nb][mt][0], ah[nb][mt][1], ah[nb][mt][2], ah[nb][mt][3], aB + aoff);
                }
            }
#pragma unroll
            for (int g = 0; g < 4; g++) {
                // 16 distinct accumulators per ks - no chaining
                MMA16816(acc[0][2 * g],     ah[cb][0][0], ah[cb][0][1], ah[cb][0][2], ah[cb][0][3], bf[cb][g].x, bf[cb][g].y);
                MMA16816(acc[0][2 * g + 1], ah[cb][0][0], ah[cb][0][1], ah[cb][0][2], ah[cb][0][3], bf[cb][g].z, bf[cb][g].w);
                MMA16816(acc[1][2 * g],     ah[cb][1][0], ah[cb][1][1], ah[cb][1][2], ah[cb][1][3], bf[cb][g].x, bf[cb][g].y);
                MMA16816(acc[1][2 * g + 1], ah[cb][1][0], ah[cb][1][1], ah[cb][1][2], ah[cb][1][3], bf[cb][g].z, bf[cb][g].w);
            }
        }
    }

    // ================= epilogue: bias + ReLU + LN =================
    float* ssum = (float*)(smem + OFF_SSUM);
    float* sssq = (float*)(smem + OFF_SSSQ);
    float* rst  = (float*)(smem + OFF_RST);

#pragma unroll
    for (int mt = 0; mt < 2; mt++) {
        float sum0 = 0.f, ssq0 = 0.f, sum1 = 0.f, ssq1 = 0.f;
#pragma unroll
        for (int t = 0; t < 8; t++) {
            int cb = wn * 64 + t * 8 + (lane & 3) * 2;
            float b0v = bias_s[cb], b1v = bias_s[cb + 1];
            float h;
            h = fmaxf(acc[mt][t][0] + b0v, 0.f); acc[mt][t][0] = h; sum0 += h; ssq0 += h * h;
            h = fmaxf(acc[mt][t][1] + b1v, 0.f); acc[mt][t][1] = h; sum0 += h; ssq0 += h * h;
            h = fmaxf(acc[mt][t][2] + b0v, 0.f); acc[mt][t][2] = h; sum1 += h; ssq1 += h * h;
            h = fmaxf(acc[mt][t][3] + b1v, 0.f); acc[mt][t][3] = h; sum1 += h; ssq1 += h * h;
        }
#pragma unroll
        for (int o = 1; o <= 2; o <<= 1) {
            sum0 += __shfl_xor_sync(0xffffffffu, sum0, o);
            ssq0 += __shfl_xor_sync(0xffffffffu, ssq0, o);
            sum1 += __shfl_xor_sync(0xffffffffu, sum1, o);
            ssq1 += __shfl_xor_sync(0xffffffffu, ssq1, o);
        }
        if ((lane & 3) == 0) {
            int r0 = mt * 16 + (lane >> 2);
            ssum[r0 * 8 + wn] = sum0;       sssq[r0 * 8 + wn] = ssq0;
            ssum[(r0 + 8) * 8 + wn] = sum1; sssq[(r0 + 8) * 8 + wn] = ssq1;
        }
    }
    __syncthreads();
    if (tid < 32) {
        float s = 0.f, q = 0.f;
#pragma unroll
        for (int i = 0; i < 8; i++) { s += ssum[tid * 8 + i]; q += sssq[tid * 8 + i]; }
        float mean = s * (1.f / 512.f);
        float var  = q * (1.f / 512.f) - mean * mean;
        rst[tid * 2] = mean;
        rst[tid * 2 + 1] = rsqrtf(var + 1e-5f);
    }
    __syncthreads();

#pragma unroll
    for (int mt = 0; mt < 2; mt++) {
        int r0 = mt * 16 + (lane >> 2);
        float m0 = rst[r0 * 2], rs0 = rst[r0 * 2 + 1];
        float m1 = rst[(r0 + 8) * 2], rs1 = rst[(r0 + 8) * 2 + 1];
        int gr0 = row0 + r0, gr1 = gr0 + 8;
        int b0i = gr0 / KSPLIT, j0 = gr0 - b0i * KSPLIT;
        int b1i = gr1 / KSPLIT, j1 = gr1 - b1i * KSPLIT;
        float* o0 = out + ((size_t)b0i * NQ + QOFF + j0) * 512;
        float* o1 = out + ((size_t)b1i * NQ + QOFF + j1) * 512;
#pragma unroll
        for (int t = 0; t < 8; t++) {
            int cb = wn * 64 + t * 8 + (lane & 3) * 2;
            float g0 = gam_s[cb], g1 = gam_s[cb + 1];
            float e0 = bet_s[cb], e1 = bet_s[cb + 1];
            float2 v0 = make_float2((acc[mt][t][0] - m0) * rs0 * g0 + e0,
                                    (acc[mt][t][1] - m0) * rs0 * g1 + e1);
            float2 v1 = make_float2((acc[mt][t][2] - m1) * rs1 * g0 + e0,
                                    (acc[mt][t][3] - m1) * rs1 * g1 + e1);
            *(float2*)(o0 + cb) = v0;
            *(float2*)(o1 + cb) = v1;
        }
    }
}

__global__ void __launch_bounds__(THREADS, 2)
fused_kernel(const float* __restrict__ x,
             const float* b0, const float* g0, const float* be0,
             const float* b1, const float* g1, const float* be1,
             const float* b2, const float* g2, const float* be2,
             float* __restrict__ out) {
    const int blk = blockIdx.x;
    if (blk < 64)         run_split<1,  400, 7, 0,     0 >(x, b0, g0, be0, out, g_w0, blk);
    else if (blk < 3904)  run_split<60, 256, 4, 400,   1 >(x, b1, g1, be1, out, g_w1, blk - 64);
    else                  run_split<36, 256, 4, 15760, 61>(x, b2, g2, be2, out, g_w2, blk - 3904);
}

// ================= weight prep: W f32 -> fp16 MMA-fragment layout =================
__device__ __forceinline__ uint32_t rdh(const float* __restrict__ W, int Lvalid, int k, int n) {
    float v = (k < Lvalid) ? W[(size_t)k * 512 + n] : 0.f;
    __half h = __float2half_rn(v);
    return (uint32_t)*(uint16_t*)&h;
}
__device__ __forceinline__ void prep_frag(const float* __restrict__ W, uint4* dst,
                                          int Lvalid, int t) {
    int lane = t & 31;
    int j    = (t >> 5) & 31;       // n16-group
    int cks  = t >> 10;             // c*4 + ks
    int k0   = cks * 16 + (lane & 3) * 2;
    int nv   = j * 16 + (lane >> 2);
    uint4 o;
    o.x = rdh(W, Lvalid, k0,     nv)     | (rdh(W, Lvalid, k0 + 1, nv)     << 16);
    o.y = rdh(W, Lvalid, k0 + 8, nv)     | (rdh(W, Lvalid, k0 + 9, nv)     << 16);
    o.z = rdh(W, Lvalid, k0,     nv + 8) | (rdh(W, Lvalid, k0 + 1, nv + 8) << 16);
    o.w = rdh(W, Lvalid, k0 + 8, nv + 8) | (rdh(W, Lvalid, k0 + 9, nv + 8) << 16);
    dst[t] = o;
}

__global__ void prep_kernel(const float* __restrict__ W0, const float* __restrict__ W1,
                            const float* __restrict__ W2) {
    const int idx = blockIdx.x * blockDim.x + threadIdx.x;
    const int T0 = 448 * 512 / 8, T1 = 256 * 512 / 8, T2 = 256 * 512 / 8;
    if (idx < T0)                prep_frag(W0, g_w0, 400, idx);
    else if (idx < T0 + T1)      prep_frag(W1, g_w1, 256, idx - T0);
    else if (idx < T0 + T1 + T2) prep_frag(W2, g_w2, 256, idx - T0 - T1);
}

// ================= launch =================
extern "C" void kernel_launch(void* const* d_in, const int* in_sizes, int n_in,
                              void* d_out, int out_size) {
    (void)in_sizes; (void)n_in; (void)out_size;
    const float* x = (const float*)d_in[0];
    float* out = (float*)d_out;

    cudaFuncSetAttribute(fused_kernel, cudaFuncAttributeMaxDynamicSharedMemorySize, SMEM_TOTAL);

    const int prep_total = (448 + 256 + 256) * 512 / 8;
    prep_kernel<<<(prep_total + 255) / 256, 256>>>(
        (const float*)d_in[1], (const float*)d_in[5], (const float*)d_in[9]);

    fused_kernel<<<6208, THREADS, SMEM_TOTAL>>>(
        x,
        (const float*)d_in[2],  (const float*)d_in[3],  (const float*)d_in[4],
        (const float*)d_in[6],  (const float*)d_in[7],  (const float*)d_in[8],
        (const float*)d_in[10], (const float*)d_in[11], (const float*)d_in[12],
        out);
}